// round 14
// baseline (speedup 1.0000x reference)
#include <cuda.h>
#include <cuda_runtime.h>
#include <cuda_bf16.h>
#include <math.h>
#include <stdint.h>

typedef __nv_bfloat16 bf16;

// Problem constants
#define BATCH 2
#define SEQL  2048
#define DIM   768
#define NHEAD 12
#define DHEAD 64
#define DFF   3072
#define DFFH  1536
#define NROWS (BATCH*SEQL)          // 4096
#define QKVLD 2304
#define KCAT  6144
#define KCHUNK 3072                 // down-proj split-K=2 chunk
#define NPERS 296                   // persistent grid (148 SMs x 2 blocks)

// ---------------- scratch (static device globals; no allocation) ----------------
__device__ float g_mask [DIM];
__device__ bf16  g_xn   [NROWS*DIM];
__device__ bf16  g_qkv  [(size_t)NROWS*QKVLD];
__device__ bf16  g_attn [NROWS*DIM];
__device__ float g_x1   [NROWS*DIM];
__device__ float g_pb   [NROWS*DIM];          // split-K partial (fp32)
__device__ bf16  g_hcat [(size_t)NROWS*KCAT];
__device__ bf16  g_wqkv [QKVLD*DIM];
__device__ bf16  g_w1cat[(size_t)KCAT*DIM];   // mask pre-folded into w1t/w1s rows
__device__ bf16  g_w2cat[(size_t)DIM*KCAT];   // 0.5 blend pre-folded
__device__ bf16  g_woc  [DIM*DIM];

// ---------------- helpers ----------------
__device__ __forceinline__ float gelu_f(float x) {
    return 0.5f * x * (1.f + erff(x * 0.70710678118654752f));
}
__device__ __forceinline__ float silu_f(float x) {
    return x / (1.f + expf(-x));
}
__device__ __forceinline__ __nv_bfloat162 pack_bf2(float a, float b) {
    return __float22bfloat162_rn(make_float2(a, b));
}
__device__ __forceinline__ void mma16(float* c, const unsigned* a,
                                      unsigned b0, unsigned b1) {
    asm volatile(
        "mma.sync.aligned.m16n8k16.row.col.f32.bf16.bf16.f32 "
        "{%0,%1,%2,%3}, {%4,%5,%6,%7}, {%8,%9}, {%0,%1,%2,%3};\n"
        : "+f"(c[0]), "+f"(c[1]), "+f"(c[2]), "+f"(c[3])
        : "r"(a[0]), "r"(a[1]), "r"(a[2]), "r"(a[3]), "r"(b0), "r"(b1));
}
__device__ __forceinline__ void ldsm4(unsigned* r, unsigned addr) {
    asm volatile("ldmatrix.sync.aligned.m8n8.x4.shared.b16 {%0,%1,%2,%3}, [%4];"
        : "=r"(r[0]), "=r"(r[1]), "=r"(r[2]), "=r"(r[3]) : "r"(addr));
}

// ---------------- TMA / mbarrier primitives (sm_90 baseline PTX) ----------------
__device__ __forceinline__ void mbar_init(unsigned a, unsigned cnt) {
    asm volatile("mbarrier.init.shared.b64 [%0], %1;" :: "r"(a), "r"(cnt) : "memory");
}
__device__ __forceinline__ void mbar_expect(unsigned a, unsigned tx) {
    asm volatile("mbarrier.arrive.expect_tx.shared.b64 _, [%0], %1;"
                 :: "r"(a), "r"(tx) : "memory");
}
__device__ __forceinline__ void mbar_wait(unsigned a, unsigned parity) {
    asm volatile(
        "{\n\t.reg .pred P;\n"
        "W%=:\n\t"
        "mbarrier.try_wait.parity.acquire.cta.shared::cta.b64 P, [%0], %1;\n\t"
        "@!P bra W%=;\n\t}"
        :: "r"(a), "r"(parity) : "memory");
}
__device__ __forceinline__ void tma2d(unsigned dst, const CUtensorMap* m,
                                      int x, int y, unsigned bar) {
    asm volatile(
        "cp.async.bulk.tensor.2d.shared::cta.global.tile.mbarrier::complete_tx::bytes "
        "[%0], [%1, {%2, %3}], [%4];"
        :: "r"(dst), "l"(m), "r"(x), "r"(y), "r"(bar) : "memory");
}

// ---------------- timelike_mask decode (dtype-robust: f32 / i32 / bool8) ----------------
__global__ void decode_mask_kernel(const void* __restrict__ raw) {
    __shared__ int cls;
    if (threadIdx.x == 0) {
        const unsigned* w = (const unsigned*)raw;
        int isFloat = 0, isByte = 0;
        for (int i = 0; i < 192; i++) {
            unsigned v = w[i];
            if (v == 0x3F800000u) isFloat = 1;
            if (v != 0u) {
                bool bytes01 = true, hi = false;
                for (int b = 0; b < 4; b++) {
                    unsigned by = (v >> (8*b)) & 0xffu;
                    if (by > 1u) bytes01 = false;
                    if (b > 0 && by) hi = true;
                }
                if (bytes01 && hi) isByte = 1;
            }
        }
        cls = isFloat ? 0 : (isByte ? 2 : 1);
    }
    __syncthreads();
    int c = cls;
    for (int i = threadIdx.x; i < DIM; i += blockDim.x) {
        float mv;
        if (c == 0)      mv = ((const float*)raw)[i];
        else if (c == 1) mv = (float)(((const int*)raw)[i] != 0);
        else             mv = (float)(((const unsigned char*)raw)[i] != 0);
        g_mask[i] = mv;
    }
}

// ---------------- fused weight prep: concat + bf16 + mask/scale folding ----------------
#define PR_S0 (QKVLD*DIM)
#define PR_S1 (PR_S0 + (size_t)KCAT*DIM)
#define PR_S2 (PR_S1 + (size_t)DIM*KCAT)
#define PR_S3 (PR_S2 + (size_t)DIM*DIM)
#define PREP_QUADS (PR_S3/4)

__global__ __launch_bounds__(256) void prep_all(
    const float* __restrict__ Wq, const float* __restrict__ Wk,
    const float* __restrict__ Wv, const float* __restrict__ Wo,
    const float* __restrict__ w1, const float* __restrict__ w1t,
    const float* __restrict__ w1s, const float* __restrict__ w2,
    const float* __restrict__ w2t, const float* __restrict__ w2s)
{
    size_t i = (size_t)(blockIdx.x * 256 + threadIdx.x) * 4;
    const float* src;
    bf16* dst;
    float m0 = 1.f, m1 = 1.f, m2 = 1.f, m3 = 1.f;
    if (i < PR_S0) {
        int r = (int)(i / DIM), c = (int)(i % DIM);
        src = (r < DIM) ? (Wq + (size_t)r*DIM + c)
            : (r < 2*DIM) ? (Wk + (size_t)(r-DIM)*DIM + c)
            : (Wv + (size_t)(r-2*DIM)*DIM + c);
        dst = g_wqkv + i;
    } else if (i < PR_S1) {
        size_t j = i - PR_S0;
        int r = (int)(j / DIM), c = (int)(j % DIM);
        if (r < DFF) {
            src = w1 + (size_t)r*DIM + c;
        } else if (r < DFF + DFFH) {
            src = w1t + (size_t)(r-DFF)*DIM + c;
            m0 = g_mask[c]; m1 = g_mask[c+1]; m2 = g_mask[c+2]; m3 = g_mask[c+3];
        } else {
            src = w1s + (size_t)(r-DFF-DFFH)*DIM + c;
            m0 = 1.f-g_mask[c]; m1 = 1.f-g_mask[c+1];
            m2 = 1.f-g_mask[c+2]; m3 = 1.f-g_mask[c+3];
        }
        dst = g_w1cat + j;
    } else if (i < PR_S2) {
        size_t j = i - PR_S1;
        int r = (int)(j / KCAT), c = (int)(j % KCAT);
        src = (c < DFF) ? (w2 + (size_t)r*DFF + c)
            : (c < DFF+DFFH) ? (w2t + (size_t)r*DFFH + c - DFF)
            : (w2s + (size_t)r*DFFH + c - DFF - DFFH);
        dst = g_w2cat + j;
        m0 = m1 = m2 = m3 = 0.5f;                 // fold FFN blend scale
    } else {
        size_t j = i - PR_S2;
        src = Wo + j;
        dst = g_woc + j;
    }
    float4 v = *(const float4*)src;
    *(__nv_bfloat162*)dst       = pack_bf2(v.x * m0, v.y * m1);
    *(__nv_bfloat162*)(dst + 2) = pack_bf2(v.z * m2, v.w * m3);
}

// ---------------- Minkowski LayerNorm (bf16 output) ----------------
__global__ __launch_bounds__(256) void mink_norm_kernel(
    const float* __restrict__ x, const float* __restrict__ w,
    const float* __restrict__ bb, bf16* __restrict__ out)
{
    __shared__ float sA[8], sB[8];
    int row = blockIdx.x, t = threadIdx.x;
    const float* xr = x + (size_t)row * DIM;
    float v0 = xr[t], v1 = xr[t+256], v2 = xr[t+512];
    int lane = t & 31, wp = t >> 5;

    float s = v0 + v1 + v2;
    #pragma unroll
    for (int o = 16; o; o >>= 1) s += __shfl_xor_sync(0xffffffffu, s, o);
    if (!lane) sA[wp] = s;
    __syncthreads();
    float tot = 0.f;
    #pragma unroll
    for (int i = 0; i < 8; i++) tot += sA[i];
    float mean = tot * (1.f / DIM);

    float c0 = v0 - mean, c1 = v1 - mean, c2 = v2 - mean;
    float m0 = g_mask[t], m1 = g_mask[t+256], m2 = g_mask[t+512];
    float s2  = c0*c0 + c1*c1 + c2*c2;
    float s2m = c0*c0*m0 + c1*c1*m1 + c2*c2*m2;
    #pragma unroll
    for (int o = 16; o; o >>= 1) {
        s2  += __shfl_xor_sync(0xffffffffu, s2,  o);
        s2m += __shfl_xor_sync(0xffffffffu, s2m, o);
    }
    __syncthreads();
    if (!lane) { sA[wp] = s2; sB[wp] = s2m; }
    __syncthreads();
    float S2 = 0.f, S2m = 0.f;
    #pragma unroll
    for (int i = 0; i < 8; i++) { S2 += sA[i]; S2m += sB[i]; }

    float var = S2 * (1.f / DIM);
    float eta = S2 - 2.f * S2m;
    float kk  = 0.5f * (rsqrtf(var + 1e-5f) + rsqrtf(fabsf(eta) + 1e-5f));

    size_t o0 = (size_t)row * DIM + t;
    out[o0]     = __float2bfloat16_rn(w[t]     * (c0 * kk) + bb[t]);
    out[o0+256] = __float2bfloat16_rn(w[t+256] * (c1 * kk) + bb[t+256]);
    out[o0+512] = __float2bfloat16_rn(w[t+512] * (c2 * kk) + bb[t+512]);
}

// ---------------- persistent TMA-fed bf16 tensor-core NT GEMM ----------------
#define TSTG 3
#define TSTB 32768
#define TC_SMEM (TSTG*TSTB + 1024)

// epilogue: OT 0 fp32(+resid, alpha), 1 bf16 (act), 2 raw fp32 partial
template<int OT>
__device__ __forceinline__ void store_epi4(
    float (&acc)[4][4][4], void* Cv, const float* __restrict__ resid,
    int ldc, float alpha, int bm, int bn, int act)
{
    int tid = threadIdx.x, lane = tid & 31, wid = tid >> 5;
    int wm = wid & 1, wn = wid >> 1;
    int g = lane >> 2, t = lane & 3;
    #pragma unroll
    for (int mt = 0; mt < 4; mt++) {
        int r0 = bm + wm*64 + mt*16 + g;
        #pragma unroll
        for (int nt = 0; nt < 4; nt++) {
            int c = bn + wn*32 + nt*8 + t*2;
            #pragma unroll
            for (int hh = 0; hh < 2; hh++) {
                float v0 = acc[mt][nt][2*hh];
                float v1 = acc[mt][nt][2*hh + 1];
                size_t idx = (size_t)(r0 + 8*hh) * ldc + c;
                if (OT == 1) {
                    if (act == 1) { v0 = gelu_f(v0); v1 = gelu_f(v1); }
                    else if (act == 2) { v0 = silu_f(v0); v1 = silu_f(v1); }
                    *(__nv_bfloat162*)((bf16*)Cv + idx) = pack_bf2(v0, v1);
                } else if (OT == 0) {
                    v0 *= alpha; v1 *= alpha;
                    if (resid) {
                        float2 rv = *(const float2*)(resid + idx);
                        v0 += rv.x; v1 += rv.y;
                    }
                    *(float2*)((float*)Cv + idx) = make_float2(v0, v1);
                } else {
                    *(float2*)((float*)Cv + idx) = make_float2(v0, v1);
                }
            }
        }
    }
}

// Persistent: grid of G blocks walks tiles t = bid + k*G over ntm x ntn x NZ tiles.
// 3-stage TMA ring runs CONTINUOUSLY across tile boundaries (no per-tile refill).
// NZ=2: split-K down-proj (z=0 -> C with resid; z=1 -> pb raw fp32).
template<int OT, int ACTSEL, int NZ>
__global__ __launch_bounds__(256, 2) void tgemm_pers(
    const __grid_constant__ CUtensorMap mapA,
    const __grid_constant__ CUtensorMap mapB,
    void* __restrict__ C, float* __restrict__ pb,
    const float* __restrict__ resid,
    int ntn, int ntm, int nk, int ldc, float alpha)
{
    extern __shared__ char tsm[];
    uintptr_t gp = (uintptr_t)tsm;
    unsigned base = (unsigned)__cvta_generic_to_shared(
        (void*)((gp + 1023) & ~(uintptr_t)1023));
    __shared__ __align__(8) unsigned long long mbar_s[TSTG];
    unsigned mb = (unsigned)__cvta_generic_to_shared(mbar_s);

    int tid = threadIdx.x, lane = tid & 31, wid = tid >> 5;
    int wm = wid & 1, wn = wid >> 1;
    int lrow = lane & 15, lu = lane >> 4;
    int G = gridDim.x, bid = blockIdx.x;

    int tilesMN = ntm * ntn;
    int ntiles = tilesMN * NZ;
    int nmy = (bid < ntiles) ? (ntiles - bid + G - 1) / G : 0;
    int mystages = nmy * nk;

    if (tid == 0) {
        #pragma unroll
        for (int s = 0; s < TSTG; s++) mbar_init(mb + 8*s, 1);
    }
    __syncthreads();

    // prefetch stage ls into ring buffer b (coords derived from linear stage idx)
    auto prefetch = [&](int ls, int b) {
        int tloc = ls / nk, kt = ls - tloc * nk;
        int t = bid + tloc * G;
        int z = t / tilesMN; int tt = t - z * tilesMN;
        int tm = tt / ntn;
        int pbm = tm * 128, pbn = (tt - tm * ntn) * 128;
        int kx = z * KCHUNK + kt * 64;
        mbar_expect(mb + 8*b, TSTB);
        tma2d(base + b*TSTB,         &mapA, kx, pbm, mb + 8*b);
        tma2d(base + b*TSTB + 16384, &mapB, kx, pbn, mb + 8*b);
    };

    if (tid == 0) {
        for (int s = 0; s < TSTG && s < mystages; s++) prefetch(s, s);
    }

    int ls = 0;
    for (int tl = 0; tl < nmy; tl++) {
        int t = bid + tl * G;
        int z = t / tilesMN; int tt = t - z * tilesMN;
        int tm = tt / ntn;
        int bm = tm * 128, bn = (tt - tm * ntn) * 128;

        float acc[4][4][4] = {};
        for (int kt = 0; kt < nk; kt++) {
            int b = ls % TSTG;
            unsigned par = (unsigned)((ls / TSTG) & 1);
            mbar_wait(mb + 8*b, par);
            unsigned stA = base + b*TSTB, stB = stA + 16384;
            #pragma unroll
            for (int ks = 0; ks < 4; ks++) {
                unsigned af[4][4], bq[2][4];
                #pragma unroll
                for (int mt = 0; mt < 4; mt++) {
                    int r = wm*64 + mt*16 + lrow;
                    ldsm4(af[mt], stA + r*128 + ((((ks<<1)|lu) ^ (r&7)) << 4));
                }
                #pragma unroll
                for (int p = 0; p < 2; p++) {
                    int r = wn*32 + p*16 + lrow;
                    ldsm4(bq[p], stB + r*128 + ((((ks<<1)|lu) ^ (r&7)) << 4));
                }
                #pragma unroll
                for (int mt = 0; mt < 4; mt++)
                    #pragma unroll
                    for (int nt = 0; nt < 4; nt++)
                        mma16(acc[mt][nt], af[mt],
                              bq[nt>>1][nt&1], bq[nt>>1][(nt&1)+2]);
            }
            __syncthreads();
            if (tid == 0 && ls + TSTG < mystages) {
                asm volatile("fence.proxy.async.shared::cta;" ::: "memory");
                prefetch(ls + TSTG, b);
            }
            ls++;
        }

        if (NZ == 2) {
            if (z == 0) store_epi4<0>(acc, C, resid, ldc, alpha, bm, bn, 0);
            else        store_epi4<2>(acc, pb, nullptr, ldc, 0.f, bm, bn, 0);
        } else {
            int act = ACTSEL ? ((bn >= DFF && bn < DFF + DFFH) ? 2 : 1) : 0;
            store_epi4<OT>(acc, C, resid, ldc, alpha, bm, bn, act);
        }
    }
}

// final: out += pb (0.5 pre-folded into w2cat)
__global__ __launch_bounds__(256) void addk(
    float* __restrict__ out, const float* __restrict__ pb)
{
    int i = blockIdx.x * 256 + threadIdx.x;
    float4 o = ((const float4*)out)[i];
    float4 p = ((const float4*)pb)[i];
    ((float4*)out)[i] = make_float4(o.x + p.x, o.y + p.y, o.z + p.z, o.w + p.w);
}

// ---------------- fold Lorentz sf + 1/sqrt(DH) into Q (bf16) ----------------
__global__ __launch_bounds__(256) void qeff_kernel(bf16* __restrict__ qkv)
{
    int gw   = (blockIdx.x * blockDim.x + threadIdx.x) >> 5;
    int lane = threadIdx.x & 31;
    if (gw >= NROWS * NHEAD) return;
    int row = gw / NHEAD, h = gw % NHEAD;
    bf16* qp = qkv + (size_t)row * QKVLD + h * DHEAD;
    float a = __bfloat162float(qp[lane]);
    float c = __bfloat162float(qp[lane + 32]);
    float ma = g_mask[h * DHEAD + lane], mc = g_mask[h * DHEAD + lane + 32];
    float qn2  = a*a + c*c;
    float qtn2 = a*a*ma + c*c*mc;
    #pragma unroll
    for (int o = 16; o; o >>= 1) {
        qn2  += __shfl_xor_sync(0xffffffffu, qn2,  o);
        qtn2 += __shfl_xor_sync(0xffffffffu, qtn2, o);
    }
    float qtn = sqrtf(qtn2);
    float sf  = (qtn > 1e-6f) ? sqrtf(qn2) / fmaxf(qtn, 1e-8f) : 0.f;
    qp[lane]      = __float2bfloat16_rn(a * (1.f - 0.5f * sf * ma) * 0.125f);
    qp[lane + 32] = __float2bfloat16_rn(c * (1.f - 0.5f * sf * mc) * 0.125f);
}

// ---------------- bf16 tensor-core causal flash attention ----------------
#define FSH 72
#define FA_SMEM ((128 + 64 + 64 + 128) * FSH * 2)   // 55296 bytes

__global__ __launch_bounds__(256) void flash_tc(
    const bf16* __restrict__ QKV, bf16* __restrict__ O)
{
    extern __shared__ char smc[];
    bf16* Qs = (bf16*)smc;
    bf16* Ks = Qs + 128 * FSH;
    bf16* Vt = Qs + 192 * FSH;
    bf16* Ps = Qs + 256 * FSH;
    unsigned smQ = (unsigned)__cvta_generic_to_shared(Qs);
    unsigned smK = smQ + 128 * FSH * 2;
    unsigned smV = smQ + 192 * FSH * 2;
    unsigned smP = smQ + 256 * FSH * 2;

    int tid = threadIdx.x, lane = tid & 31, wid = tid >> 5;
    int g = lane >> 2, t = lane & 3;
    int lrow = lane & 15, lk8 = (lane >> 4) << 3;
    int bid = blockIdx.x;
    int qb = 15 - bid / 24;
    int bh = bid % 24;
    int b = bh / NHEAD, h = bh % NHEAD;

    const bf16* Qp = QKV + (size_t)(b * SEQL + qb * 128) * QKVLD + h * DHEAD;
    const bf16* Kp = QKV + (size_t)(b * SEQL) * QKVLD + DIM + h * DHEAD;
    const bf16* Vp = Kp + DIM;

    #pragma unroll
    for (int it = 0; it < 4; it++) {
        int idx = tid + it * 256;
        int r = idx >> 3, c8 = (idx & 7) * 8;
        *(uint4*)&Qs[r * FSH + c8] = *(const uint4*)(Qp + (size_t)r * QKVLD + c8);
    }

    float oacc[8][4] = {};
    float mrun[2] = {-1e30f, -1e30f}, lrun[2] = {0.f, 0.f};
    int rbase = qb * 128 + wid * 16;
    int kmax = 2 * qb + 2;

    for (int kt = 0; kt < kmax; kt++) {
        __syncthreads();
        #pragma unroll
        for (int it = 0; it < 2; it++) {
            int idx = tid + it * 256;
            int r = idx >> 3, c8 = (idx & 7) * 8;
            *(uint4*)&Ks[r * FSH + c8] =
                *(const uint4*)(Kp + (size_t)(kt * 64 + r) * QKVLD + c8);
            uint4 vv = *(const uint4*)(Vp + (size_t)(kt * 64 + r) * QKVLD + c8);
            const bf16* vh = (const bf16*)&vv;
            #pragma unroll
            for (int e = 0; e < 8; e++)
                Vt[(c8 + e) * FSH + r] = vh[e];
        }
        __syncthreads();

        float s[8][4] = {};
        #pragma unroll
        for (int ks = 0; ks < 4; ks++) {
            unsigned aq[4], bk[4][4];
            ldsm4(aq, smQ + ((wid*16 + lrow)*FSH + ks*16 + lk8)*2);
            #pragma unroll
            for (int p = 0; p < 4; p++)
                ldsm4(bk[p], smK + ((p*16 + lrow)*FSH + ks*16 + lk8)*2);
            #pragma unroll
            for (int nt = 0; nt < 8; nt++)
                mma16(s[nt], aq, bk[nt>>1][nt&1], bk[nt>>1][(nt&1)+2]);
        }

        if (kt * 64 + 63 > rbase) {
            int r0 = rbase + g, r1 = r0 + 8;
            #pragma unroll
            for (int nt = 0; nt < 8; nt++) {
                int c0 = kt * 64 + nt * 8 + t * 2;
                if (c0     > r0) s[nt][0] = -1e30f;
                if (c0 + 1 > r0) s[nt][1] = -1e30f;
                if (c0     > r1) s[nt][2] = -1e30f;
                if (c0 + 1 > r1) s[nt][3] = -1e30f;
            }
        }

        #pragma unroll
        for (int r = 0; r < 2; r++) {
            float rm = -1e30f;
            #pragma unroll
            for (int nt = 0; nt < 8; nt++)
                rm = fmaxf(rm, fmaxf(s[nt][2*r], s[nt][2*r + 1]));
            rm = fmaxf(rm, __shfl_xor_sync(0xffffffffu, rm, 1));
            rm = fmaxf(rm, __shfl_xor_sync(0xffffffffu, rm, 2));
            float mn = fmaxf(mrun[r], rm);
            float sc = __expf(mrun[r] - mn);
            float rs = 0.f;
            #pragma unroll
            for (int nt = 0; nt < 8; nt++) {
                s[nt][2*r]     = __expf(s[nt][2*r]     - mn);
                s[nt][2*r + 1] = __expf(s[nt][2*r + 1] - mn);
                rs += s[nt][2*r] + s[nt][2*r + 1];
            }
            rs += __shfl_xor_sync(0xffffffffu, rs, 1);
            rs += __shfl_xor_sync(0xffffffffu, rs, 2);
            lrun[r] = lrun[r] * sc + rs;
            mrun[r] = mn;
            #pragma unroll
            for (int nt = 0; nt < 8; nt++) {
                oacc[nt][2*r]     *= sc;
                oacc[nt][2*r + 1] *= sc;
            }
        }

        #pragma unroll
        for (int nt = 0; nt < 8; nt++) {
            int c = nt * 8 + t * 2;
            *(__nv_bfloat162*)&Ps[(wid*16 + g    ) * FSH + c] = pack_bf2(s[nt][0], s[nt][1]);
            *(__nv_bfloat162*)&Ps[(wid*16 + g + 8) * FSH + c] = pack_bf2(s[nt][2], s[nt][3]);
        }
        __syncwarp();

        #pragma unroll
        for (int ks = 0; ks < 4; ks++) {
            unsigned ap[4], bv[4][4];
            ldsm4(ap, smP + ((wid*16 + lrow)*FSH + ks*16 + lk8)*2);
            #pragma unroll
            for (int p = 0; p < 4; p++)
                ldsm4(bv[p], smV + ((p*16 + lrow)*FSH + ks*16 + lk8)*2);
            #pragma unroll
            for (int nt = 0; nt < 8; nt++)
                mma16(oacc[nt], ap, bv[nt>>1][nt&1], bv[nt>>1][(nt&1)+2]);
        }
    }

    float i0 = 1.f / lrun[0], i1 = 1.f / lrun[1];
    size_t grow0 = (size_t)b * SEQL + qb * 128 + wid * 16 + g;
    #pragma unroll
    for (int nt = 0; nt < 8; nt++) {
        int c = h * DHEAD + nt * 8 + t * 2;
        *(__nv_bfloat162*)&O[grow0 * DIM + c] =
            pack_bf2(oacc[nt][0] * i0, oacc[nt][1] * i0);
        *(__nv_bfloat162*)&O[(grow0 + 8) * DIM + c] =
            pack_bf2(oacc[nt][2] * i1, oacc[nt][3] * i1);
    }
}

// ---------------- host launcher ----------------
typedef CUresult (*tmap_fn_t)(
    CUtensorMap*, CUtensorMapDataType, cuuint32_t, void*,
    const cuuint64_t*, const cuuint64_t*, const cuuint32_t*, const cuuint32_t*,
    CUtensorMapInterleave, CUtensorMapSwizzle, CUtensorMapL2promotion,
    CUtensorMapFloatOOBfill);

static void encode_map(tmap_fn_t fn, CUtensorMap* m, void* p,
                       unsigned long long Kd, unsigned long long Md) {
    cuuint64_t dims[2]    = {Kd, Md};
    cuuint64_t strides[1] = {Kd * 2};
    cuuint32_t box[2]     = {64, 128};
    cuuint32_t es[2]      = {1, 1};
    fn(m, CU_TENSOR_MAP_DATA_TYPE_BFLOAT16, 2, p, dims, strides, box, es,
       CU_TENSOR_MAP_INTERLEAVE_NONE, CU_TENSOR_MAP_SWIZZLE_128B,
       CU_TENSOR_MAP_L2_PROMOTION_L2_128B, CU_TENSOR_MAP_FLOAT_OOB_FILL_NONE);
}

extern "C" void kernel_launch(void* const* d_in, const int* in_sizes, int n_in,
                              void* d_out, int out_size)
{
    const float* x    = (const float*)d_in[0];
    const void*  tmsk = d_in[2];
    const float* Wq   = (const float*)d_in[3];
    const float* Wk   = (const float*)d_in[4];
    const float* Wv   = (const float*)d_in[5];
    const float* Wo   = (const float*)d_in[6];
    const float* w1   = (const float*)d_in[7];
    const float* w2   = (const float*)d_in[8];
    const float* w1t  = (const float*)d_in[9];
    const float* w2t  = (const float*)d_in[10];
    const float* w1s  = (const float*)d_in[11];
    const float* w2s  = (const float*)d_in[12];
    const float* n1w  = (const float*)d_in[13];
    const float* n1b  = (const float*)d_in[14];
    const float* n2w  = (const float*)d_in[15];
    const float* n2b  = (const float*)d_in[16];
    float* out = (float*)d_out;

    bf16 *p_xn, *p_qkv, *p_attn, *p_hcat;
    bf16 *p_wqkv, *p_w1cat, *p_w2cat, *p_woc;
    float *p_x1, *p_pb;
    cudaGetSymbolAddress((void**)&p_xn,    g_xn);
    cudaGetSymbolAddress((void**)&p_qkv,   g_qkv);
    cudaGetSymbolAddress((void**)&p_attn,  g_attn);
    cudaGetSymbolAddress((void**)&p_x1,    g_x1);
    cudaGetSymbolAddress((void**)&p_pb,    g_pb);
    cudaGetSymbolAddress((void**)&p_hcat,  g_hcat);
    cudaGetSymbolAddress((void**)&p_wqkv,  g_wqkv);
    cudaGetSymbolAddress((void**)&p_w1cat, g_w1cat);
    cudaGetSymbolAddress((void**)&p_w2cat, g_w2cat);
    cudaGetSymbolAddress((void**)&p_woc,   g_woc);

    static tmap_fn_t tmap_fn = nullptr;
    static int attr_done = 0;
    if (!attr_done) {
        cudaFuncSetAttribute((const void*)tgemm_pers<1,0,1>, cudaFuncAttributeMaxDynamicSharedMemorySize, TC_SMEM);
        cudaFuncSetAttribute((const void*)tgemm_pers<0,0,1>, cudaFuncAttributeMaxDynamicSharedMemorySize, TC_SMEM);
        cudaFuncSetAttribute((const void*)tgemm_pers<1,1,1>, cudaFuncAttributeMaxDynamicSharedMemorySize, TC_SMEM);
        cudaFuncSetAttribute((const void*)tgemm_pers<0,0,2>, cudaFuncAttributeMaxDynamicSharedMemorySize, TC_SMEM);
        cudaFuncSetAttribute((const void*)flash_tc,          cudaFuncAttributeMaxDynamicSharedMemorySize, FA_SMEM);
        cudaDriverEntryPointQueryResult qr;
        cudaGetDriverEntryPoint("cuTensorMapEncodeTiled", (void**)&tmap_fn,
                                cudaEnableDefault, &qr);
        attr_done = 1;
    }

    // tensormaps (encoded on host; captured as kernel params)
    CUtensorMap mXn, mAttn, mHcat, mWqkv, mWoc, mW1, mW2;
    encode_map(tmap_fn, &mXn,   p_xn,    DIM,  NROWS);
    encode_map(tmap_fn, &mAttn, p_attn,  DIM,  NROWS);
    encode_map(tmap_fn, &mHcat, p_hcat,  KCAT, NROWS);
    encode_map(tmap_fn, &mWqkv, p_wqkv,  DIM,  QKVLD);
    encode_map(tmap_fn, &mWoc,  p_woc,   DIM,  DIM);
    encode_map(tmap_fn, &mW1,   p_w1cat, DIM,  KCAT);
    encode_map(tmap_fn, &mW2,   p_w2cat, KCAT, DIM);

    decode_mask_kernel<<<1, 256>>>(tmsk);
    prep_all<<<PREP_QUADS/256, 256>>>(Wq, Wk, Wv, Wo, w1, w1t, w1s, w2, w2t, w2s);

    // ---- attention path ----
    mink_norm_kernel<<<NROWS, 256>>>(x, n1w, n1b, p_xn);

    // QKV: 576 tiles, persistent over 296 blocks
    tgemm_pers<1,0,1><<<NPERS, 256, TC_SMEM>>>(
        mXn, mWqkv, p_qkv, nullptr, nullptr, QKVLD/128, NROWS/128, DIM/64,
        QKVLD, 1.f);
    qeff_kernel<<<(NROWS * NHEAD * 32) / 256, 256>>>(p_qkv);

    flash_tc<<<16 * 24, 256, FA_SMEM>>>(p_qkv, p_attn);

    // x1 = x + attn @ Wo^T  (192 tiles)
    tgemm_pers<0,0,1><<<192, 256, TC_SMEM>>>(
        mAttn, mWoc, p_x1, nullptr, x, DIM/128, NROWS/128, DIM/64, DIM, 1.f);

    // ---- FFN path ----
    mink_norm_kernel<<<NROWS, 256>>>(p_x1, n2w, n2b, p_xn);

    // fused up-projections: 1536 tiles persistent
    tgemm_pers<1,1,1><<<NPERS, 256, TC_SMEM>>>(
        mXn, mW1, p_hcat, nullptr, nullptr, KCAT/128, NROWS/128, DIM/64,
        KCAT, 1.f);

    // down-projection split-K=2 persistent: 384 tiles (z=0: out=x1+lo ; z=1: pb=hi)
    tgemm_pers<0,0,2><<<NPERS, 256, TC_SMEM>>>(
        mHcat, mW2, out, p_pb, p_x1, DIM/128, NROWS/128, KCHUNK/64, DIM, 1.f);

    // out += pb
    addk<<<NROWS*DIM/4/256, 256>>>(out, p_pb);
}

// round 15
// speedup vs baseline: 1.0583x; 1.0583x over previous
#include <cuda.h>
#include <cuda_runtime.h>
#include <cuda_bf16.h>
#include <math.h>
#include <stdint.h>

typedef __nv_bfloat16 bf16;

// Problem constants
#define BATCH 2
#define SEQL  2048
#define DIM   768
#define NHEAD 12
#define DHEAD 64
#define DFF   3072
#define DFFH  1536
#define NROWS (BATCH*SEQL)          // 4096
#define QKVLD 2304
#define KCAT  6144
#define KSPLIT 4
#define KCHUNK (KCAT/KSPLIT)        // 1536

// ---------------- scratch (static device globals; no allocation) ----------------
__device__ float g_mask [DIM];
__device__ bf16  g_xn   [NROWS*DIM];
__device__ bf16  g_qkv  [(size_t)NROWS*QKVLD];
__device__ bf16  g_attn [NROWS*DIM];
__device__ float g_x1   [NROWS*DIM];
__device__ float g_pb   [(KSPLIT-1)][NROWS*DIM];   // split-K partials (fp32)
__device__ bf16  g_hcat [(size_t)NROWS*KCAT];
__device__ bf16  g_wqkv [QKVLD*DIM];
__device__ bf16  g_w1cat[(size_t)KCAT*DIM];   // mask pre-folded into w1t/w1s rows
__device__ bf16  g_w2cat[(size_t)DIM*KCAT];   // 0.5 blend pre-folded
__device__ bf16  g_woc  [DIM*DIM];

// ---------------- helpers ----------------
__device__ __forceinline__ float gelu_f(float x) {
    return 0.5f * x * (1.f + erff(x * 0.70710678118654752f));
}
__device__ __forceinline__ float silu_f(float x) {
    return x / (1.f + expf(-x));
}
__device__ __forceinline__ __nv_bfloat162 pack_bf2(float a, float b) {
    return __float22bfloat162_rn(make_float2(a, b));
}
__device__ __forceinline__ void mma16(float* c, const unsigned* a,
                                      unsigned b0, unsigned b1) {
    asm volatile(
        "mma.sync.aligned.m16n8k16.row.col.f32.bf16.bf16.f32 "
        "{%0,%1,%2,%3}, {%4,%5,%6,%7}, {%8,%9}, {%0,%1,%2,%3};\n"
        : "+f"(c[0]), "+f"(c[1]), "+f"(c[2]), "+f"(c[3])
        : "r"(a[0]), "r"(a[1]), "r"(a[2]), "r"(a[3]), "r"(b0), "r"(b1));
}
__device__ __forceinline__ void ldsm4(unsigned* r, unsigned addr) {
    asm volatile("ldmatrix.sync.aligned.m8n8.x4.shared.b16 {%0,%1,%2,%3}, [%4];"
        : "=r"(r[0]), "=r"(r[1]), "=r"(r[2]), "=r"(r[3]) : "r"(addr));
}

// ---------------- TMA / mbarrier primitives (sm_90 baseline PTX) ----------------
__device__ __forceinline__ void mbar_init(unsigned a, unsigned cnt) {
    asm volatile("mbarrier.init.shared.b64 [%0], %1;" :: "r"(a), "r"(cnt) : "memory");
}
__device__ __forceinline__ void mbar_expect(unsigned a, unsigned tx) {
    asm volatile("mbarrier.arrive.expect_tx.shared.b64 _, [%0], %1;"
                 :: "r"(a), "r"(tx) : "memory");
}
__device__ __forceinline__ void mbar_wait(unsigned a, unsigned parity) {
    asm volatile(
        "{\n\t.reg .pred P;\n"
        "W%=:\n\t"
        "mbarrier.try_wait.parity.acquire.cta.shared::cta.b64 P, [%0], %1;\n\t"
        "@!P bra W%=;\n\t}"
        :: "r"(a), "r"(parity) : "memory");
}
__device__ __forceinline__ void tma2d(unsigned dst, const CUtensorMap* m,
                                      int x, int y, unsigned bar) {
    asm volatile(
        "cp.async.bulk.tensor.2d.shared::cta.global.tile.mbarrier::complete_tx::bytes "
        "[%0], [%1, {%2, %3}], [%4];"
        :: "r"(dst), "l"(m), "r"(x), "r"(y), "r"(bar) : "memory");
}

// ---------------- timelike_mask decode (dtype-robust: f32 / i32 / bool8) ----------------
__global__ void decode_mask_kernel(const void* __restrict__ raw) {
    __shared__ int cls;
    if (threadIdx.x == 0) {
        const unsigned* w = (const unsigned*)raw;
        int isFloat = 0, isByte = 0;
        for (int i = 0; i < 192; i++) {
            unsigned v = w[i];
            if (v == 0x3F800000u) isFloat = 1;
            if (v != 0u) {
                bool bytes01 = true, hi = false;
                for (int b = 0; b < 4; b++) {
                    unsigned by = (v >> (8*b)) & 0xffu;
                    if (by > 1u) bytes01 = false;
                    if (b > 0 && by) hi = true;
                }
                if (bytes01 && hi) isByte = 1;
            }
        }
        cls = isFloat ? 0 : (isByte ? 2 : 1);
    }
    __syncthreads();
    int c = cls;
    for (int i = threadIdx.x; i < DIM; i += blockDim.x) {
        float mv;
        if (c == 0)      mv = ((const float*)raw)[i];
        else if (c == 1) mv = (float)(((const int*)raw)[i] != 0);
        else             mv = (float)(((const unsigned char*)raw)[i] != 0);
        g_mask[i] = mv;
    }
}

// ---------------- fused weight prep: concat + bf16 + mask/scale folding ----------------
#define PR_S0 (QKVLD*DIM)
#define PR_S1 (PR_S0 + (size_t)KCAT*DIM)
#define PR_S2 (PR_S1 + (size_t)DIM*KCAT)
#define PR_S3 (PR_S2 + (size_t)DIM*DIM)
#define PREP_QUADS (PR_S3/4)

__global__ __launch_bounds__(256) void prep_all(
    const float* __restrict__ Wq, const float* __restrict__ Wk,
    const float* __restrict__ Wv, const float* __restrict__ Wo,
    const float* __restrict__ w1, const float* __restrict__ w1t,
    const float* __restrict__ w1s, const float* __restrict__ w2,
    const float* __restrict__ w2t, const float* __restrict__ w2s)
{
    size_t i = (size_t)(blockIdx.x * 256 + threadIdx.x) * 4;
    const float* src;
    bf16* dst;
    float m0 = 1.f, m1 = 1.f, m2 = 1.f, m3 = 1.f;
    if (i < PR_S0) {
        int r = (int)(i / DIM), c = (int)(i % DIM);
        src = (r < DIM) ? (Wq + (size_t)r*DIM + c)
            : (r < 2*DIM) ? (Wk + (size_t)(r-DIM)*DIM + c)
            : (Wv + (size_t)(r-2*DIM)*DIM + c);
        dst = g_wqkv + i;
    } else if (i < PR_S1) {
        size_t j = i - PR_S0;
        int r = (int)(j / DIM), c = (int)(j % DIM);
        if (r < DFF) {
            src = w1 + (size_t)r*DIM + c;
        } else if (r < DFF + DFFH) {
            src = w1t + (size_t)(r-DFF)*DIM + c;
            m0 = g_mask[c]; m1 = g_mask[c+1]; m2 = g_mask[c+2]; m3 = g_mask[c+3];
        } else {
            src = w1s + (size_t)(r-DFF-DFFH)*DIM + c;
            m0 = 1.f-g_mask[c]; m1 = 1.f-g_mask[c+1];
            m2 = 1.f-g_mask[c+2]; m3 = 1.f-g_mask[c+3];
        }
        dst = g_w1cat + j;
    } else if (i < PR_S2) {
        size_t j = i - PR_S1;
        int r = (int)(j / KCAT), c = (int)(j % KCAT);
        src = (c < DFF) ? (w2 + (size_t)r*DFF + c)
            : (c < DFF+DFFH) ? (w2t + (size_t)r*DFFH + c - DFF)
            : (w2s + (size_t)r*DFFH + c - DFF - DFFH);
        dst = g_w2cat + j;
        m0 = m1 = m2 = m3 = 0.5f;                 // fold FFN blend scale
    } else {
        size_t j = i - PR_S2;
        src = Wo + j;
        dst = g_woc + j;
    }
    float4 v = *(const float4*)src;
    *(__nv_bfloat162*)dst       = pack_bf2(v.x * m0, v.y * m1);
    *(__nv_bfloat162*)(dst + 2) = pack_bf2(v.z * m2, v.w * m3);
}

// ---------------- Minkowski LayerNorm (bf16 output) ----------------
__global__ __launch_bounds__(256) void mink_norm_kernel(
    const float* __restrict__ x, const float* __restrict__ w,
    const float* __restrict__ bb, bf16* __restrict__ out)
{
    __shared__ float sA[8], sB[8];
    int row = blockIdx.x, t = threadIdx.x;
    const float* xr = x + (size_t)row * DIM;
    float v0 = xr[t], v1 = xr[t+256], v2 = xr[t+512];
    int lane = t & 31, wp = t >> 5;

    float s = v0 + v1 + v2;
    #pragma unroll
    for (int o = 16; o; o >>= 1) s += __shfl_xor_sync(0xffffffffu, s, o);
    if (!lane) sA[wp] = s;
    __syncthreads();
    float tot = 0.f;
    #pragma unroll
    for (int i = 0; i < 8; i++) tot += sA[i];
    float mean = tot * (1.f / DIM);

    float c0 = v0 - mean, c1 = v1 - mean, c2 = v2 - mean;
    float m0 = g_mask[t], m1 = g_mask[t+256], m2 = g_mask[t+512];
    float s2  = c0*c0 + c1*c1 + c2*c2;
    float s2m = c0*c0*m0 + c1*c1*m1 + c2*c2*m2;
    #pragma unroll
    for (int o = 16; o; o >>= 1) {
        s2  += __shfl_xor_sync(0xffffffffu, s2,  o);
        s2m += __shfl_xor_sync(0xffffffffu, s2m, o);
    }
    __syncthreads();
    if (!lane) { sA[wp] = s2; sB[wp] = s2m; }
    __syncthreads();
    float S2 = 0.f, S2m = 0.f;
    #pragma unroll
    for (int i = 0; i < 8; i++) { S2 += sA[i]; S2m += sB[i]; }

    float var = S2 * (1.f / DIM);
    float eta = S2 - 2.f * S2m;
    float kk  = 0.5f * (rsqrtf(var + 1e-5f) + rsqrtf(fabsf(eta) + 1e-5f));

    size_t o0 = (size_t)row * DIM + t;
    out[o0]     = __float2bfloat16_rn(w[t]     * (c0 * kk) + bb[t]);
    out[o0+256] = __float2bfloat16_rn(w[t+256] * (c1 * kk) + bb[t+256]);
    out[o0+512] = __float2bfloat16_rn(w[t+512] * (c2 * kk) + bb[t+512]);
}

// ---------------- TMA-fed bf16 tensor-core NT GEMM ----------------
#define TSTG 3
#define TSTB 32768
#define TC_SMEM (TSTG*TSTB + 1024)

__device__ __forceinline__ void gemm_tma_core(
    const CUtensorMap& mapA, const CUtensorMap& mapB,
    int k0, int nk, int bm, int bn, float (&acc)[4][4][4])
{
    extern __shared__ char tsm[];
    uintptr_t gp = (uintptr_t)tsm;
    unsigned base = (unsigned)__cvta_generic_to_shared(
        (void*)((gp + 1023) & ~(uintptr_t)1023));
    __shared__ __align__(8) unsigned long long mbar_s[TSTG];
    unsigned mb = (unsigned)__cvta_generic_to_shared(mbar_s);

    int tid = threadIdx.x, lane = tid & 31, wid = tid >> 5;
    int wm = wid & 1, wn = wid >> 1;
    int lrow = lane & 15, lu = lane >> 4;

    if (tid == 0) {
        #pragma unroll
        for (int s = 0; s < TSTG; s++) mbar_init(mb + 8*s, 1);
    }
    __syncthreads();
    if (tid == 0) {
        for (int s = 0; s < TSTG && s < nk; s++) {
            mbar_expect(mb + 8*s, TSTB);
            tma2d(base + s*TSTB,         &mapA, k0 + s*64, bm, mb + 8*s);
            tma2d(base + s*TSTB + 16384, &mapB, k0 + s*64, bn, mb + 8*s);
        }
    }

    int b = 0, par = 0;
    for (int kt = 0; kt < nk; kt++) {
        mbar_wait(mb + 8*b, (unsigned)par);
        unsigned stA = base + b*TSTB, stB = stA + 16384;
        #pragma unroll
        for (int ks = 0; ks < 4; ks++) {
            unsigned af[4][4], bq[2][4];
            #pragma unroll
            for (int mt = 0; mt < 4; mt++) {
                int r = wm*64 + mt*16 + lrow;
                ldsm4(af[mt], stA + r*128 + ((((ks<<1)|lu) ^ (r&7)) << 4));
            }
            #pragma unroll
            for (int p = 0; p < 2; p++) {
                int r = wn*32 + p*16 + lrow;
                ldsm4(bq[p], stB + r*128 + ((((ks<<1)|lu) ^ (r&7)) << 4));
            }
            #pragma unroll
            for (int mt = 0; mt < 4; mt++)
                #pragma unroll
                for (int nt = 0; nt < 4; nt++)
                    mma16(acc[mt][nt], af[mt],
                          bq[nt>>1][nt&1], bq[nt>>1][(nt&1)+2]);
        }
        __syncthreads();
        if (tid == 0 && kt + TSTG < nk) {
            asm volatile("fence.proxy.async.shared::cta;" ::: "memory");
            mbar_expect(mb + 8*b, TSTB);
            tma2d(stA, &mapA, k0 + (kt + TSTG)*64, bm, mb + 8*b);
            tma2d(stB, &mapB, k0 + (kt + TSTG)*64, bn, mb + 8*b);
        }
        if (++b == TSTG) { b = 0; par ^= 1; }
    }
}

// epilogue: OT 0 fp32(+resid, alpha), 1 bf16 (act), 2 raw fp32 partial
template<int OT>
__device__ __forceinline__ void store_epi4(
    float (&acc)[4][4][4], void* Cv, const float* __restrict__ resid,
    int ldc, float alpha, int bm, int bn, int act)
{
    int tid = threadIdx.x, lane = tid & 31, wid = tid >> 5;
    int wm = wid & 1, wn = wid >> 1;
    int g = lane >> 2, t = lane & 3;
    #pragma unroll
    for (int mt = 0; mt < 4; mt++) {
        int r0 = bm + wm*64 + mt*16 + g;
        #pragma unroll
        for (int nt = 0; nt < 4; nt++) {
            int c = bn + wn*32 + nt*8 + t*2;
            #pragma unroll
            for (int hh = 0; hh < 2; hh++) {
                float v0 = acc[mt][nt][2*hh];
                float v1 = acc[mt][nt][2*hh + 1];
                size_t idx = (size_t)(r0 + 8*hh) * ldc + c;
                if (OT == 1) {
                    if (act == 1) { v0 = gelu_f(v0); v1 = gelu_f(v1); }
                    else if (act == 2) { v0 = silu_f(v0); v1 = silu_f(v1); }
                    *(__nv_bfloat162*)((bf16*)Cv + idx) = pack_bf2(v0, v1);
                } else if (OT == 0) {
                    v0 *= alpha; v1 *= alpha;
                    if (resid) {
                        float2 rv = *(const float2*)(resid + idx);
                        v0 += rv.x; v1 += rv.y;
                    }
                    *(float2*)((float*)Cv + idx) = make_float2(v0, v1);
                } else {
                    *(float2*)((float*)Cv + idx) = make_float2(v0, v1);
                }
            }
        }
    }
}

// fused Lorentz-qeff epilogue for Q tiles (bn < DIM):
// per-row (64-col head) norms via lane shuffles + warp-pair smem exchange,
// then store bf16 of acc * (1 - 0.5*sf*m) * 0.125.
__device__ void store_epi_qeff(
    float (&acc)[4][4][4], bf16* __restrict__ C, int ldc, int bm, int bn)
{
    extern __shared__ char tsm[];
    float* sred = (float*)tsm;                 // [8 warps][64 rows][2]
    int tid = threadIdx.x, lane = tid & 31, wid = tid >> 5;
    int wm = wid & 1, wn = wid >> 1;
    int g = lane >> 2, t = lane & 3;
    int pw = wid ^ 2;                          // partner warp: same wm, wn^1

    float mcol[4][2];
    #pragma unroll
    for (int nt = 0; nt < 4; nt++) {
        int c = bn + wn*32 + nt*8 + t*2;
        mcol[nt][0] = g_mask[c];
        mcol[nt][1] = g_mask[c + 1];
    }

    float qn[8], qt[8];
    #pragma unroll
    for (int mt = 0; mt < 4; mt++)
        #pragma unroll
        for (int hh = 0; hh < 2; hh++) {
            float a = 0.f, b = 0.f;
            #pragma unroll
            for (int nt = 0; nt < 4; nt++) {
                float v0 = acc[mt][nt][2*hh], v1 = acc[mt][nt][2*hh + 1];
                a += v0*v0 + v1*v1;
                b += v0*v0*mcol[nt][0] + v1*v1*mcol[nt][1];
            }
            a += __shfl_xor_sync(0xffffffffu, a, 1);
            b += __shfl_xor_sync(0xffffffffu, b, 1);
            a += __shfl_xor_sync(0xffffffffu, a, 2);
            b += __shfl_xor_sync(0xffffffffu, b, 2);
            qn[mt*2 + hh] = a; qt[mt*2 + hh] = b;
        }

    __syncthreads();       // smem free after mainloop; order writes below
    if (t == 0) {
        #pragma unroll
        for (int i = 0; i < 8; i++) {
            int row = (i >> 1) * 16 + g + 8 * (i & 1);
            sred[(wid*64 + row)*2 + 0] = qn[i];
            sred[(wid*64 + row)*2 + 1] = qt[i];
        }
    }
    __syncthreads();

    #pragma unroll
    for (int mt = 0; mt < 4; mt++)
        #pragma unroll
        for (int hh = 0; hh < 2; hh++) {
            int row = mt*16 + g + 8*hh;
            float a = qn[mt*2 + hh] + sred[(pw*64 + row)*2 + 0];
            float b = qt[mt*2 + hh] + sred[(pw*64 + row)*2 + 1];
            float qtn = sqrtf(b);
            float sf = (qtn > 1e-6f) ? sqrtf(a) / fmaxf(qtn, 1e-8f) : 0.f;
            int r0 = bm + wm*64 + row;
            #pragma unroll
            for (int nt = 0; nt < 4; nt++) {
                int c = bn + wn*32 + nt*8 + t*2;
                float v0 = acc[mt][nt][2*hh]   * (1.f - 0.5f*sf*mcol[nt][0]) * 0.125f;
                float v1 = acc[mt][nt][2*hh+1] * (1.f - 0.5f*sf*mcol[nt][1]) * 0.125f;
                *(__nv_bfloat162*)(C + (size_t)r0*ldc + c) = pack_bf2(v0, v1);
            }
        }
}

template<int OT, int ACTSEL, int QEFF>
__global__ __launch_bounds__(256, 2) void tgemm_tma(
    const __grid_constant__ CUtensorMap mapA,
    const __grid_constant__ CUtensorMap mapB,
    void* __restrict__ C, const float* __restrict__ resid,
    int K, int ldc, float alpha)
{
    int bm = blockIdx.y * 128, bn = blockIdx.x * 128;
    float acc[4][4][4] = {};
    gemm_tma_core(mapA, mapB, 0, K >> 6, bm, bn, acc);
    if (QEFF && bn < DIM) {
        store_epi_qeff(acc, (bf16*)C, ldc, bm, bn);
    } else {
        int act = ACTSEL ? ((bn >= DFF && bn < DFF + DFFH) ? 2 : 1) : 0;
        store_epi4<OT>(acc, C, resid, ldc, alpha, bm, bn, act);
    }
}

// split-K down-projection (0.5 pre-folded into w2cat):
// z=0 -> out = x1 + chunk0 ; z>=1 -> pb[z-1] = chunk_z (raw fp32)
__global__ __launch_bounds__(256, 2) void tgemm_down(
    const __grid_constant__ CUtensorMap mapA,
    const __grid_constant__ CUtensorMap mapB,
    float* __restrict__ out, float* __restrict__ pb0,
    const float* __restrict__ resid)
{
    int bm = blockIdx.y * 128, bn = blockIdx.x * 128;
    int z = blockIdx.z;
    float acc[4][4][4] = {};
    gemm_tma_core(mapA, mapB, z * KCHUNK, KCHUNK >> 6, bm, bn, acc);
    if (z == 0) store_epi4<0>(acc, out, resid, DIM, 1.f, bm, bn, 0);
    else        store_epi4<2>(acc, pb0 + (size_t)(z-1)*NROWS*DIM, nullptr,
                              DIM, 0.f, bm, bn, 0);
}

// final: out += pb0 + pb1 + pb2  (scales pre-folded)
__global__ __launch_bounds__(256) void addk4(
    float* __restrict__ out, const float* __restrict__ pb)
{
    int i = blockIdx.x * 256 + threadIdx.x;
    float4 o  = ((const float4*)out)[i];
    float4 p0 = ((const float4*)(pb))[i];
    float4 p1 = ((const float4*)(pb + (size_t)NROWS*DIM))[i];
    float4 p2 = ((const float4*)(pb + (size_t)2*NROWS*DIM))[i];
    ((float4*)out)[i] = make_float4(o.x + p0.x + p1.x + p2.x,
                                    o.y + p0.y + p1.y + p2.y,
                                    o.z + p0.z + p1.z + p2.z,
                                    o.w + p0.w + p1.w + p2.w);
}

// ---------------- bf16 tensor-core causal flash attention ----------------
#define FSH 72
#define FA_SMEM ((128 + 64 + 64 + 128) * FSH * 2)   // 55296 bytes

__global__ __launch_bounds__(256) void flash_tc(
    const bf16* __restrict__ QKV, bf16* __restrict__ O)
{
    extern __shared__ char smc[];
    bf16* Qs = (bf16*)smc;
    bf16* Ks = Qs + 128 * FSH;
    bf16* Vt = Qs + 192 * FSH;
    bf16* Ps = Qs + 256 * FSH;
    unsigned smQ = (unsigned)__cvta_generic_to_shared(Qs);
    unsigned smK = smQ + 128 * FSH * 2;
    unsigned smV = smQ + 192 * FSH * 2;
    unsigned smP = smQ + 256 * FSH * 2;

    int tid = threadIdx.x, lane = tid & 31, wid = tid >> 5;
    int g = lane >> 2, t = lane & 3;
    int lrow = lane & 15, lk8 = (lane >> 4) << 3;
    int bid = blockIdx.x;
    int qb = 15 - bid / 24;
    int bh = bid % 24;
    int b = bh / NHEAD, h = bh % NHEAD;

    const bf16* Qp = QKV + (size_t)(b * SEQL + qb * 128) * QKVLD + h * DHEAD;
    const bf16* Kp = QKV + (size_t)(b * SEQL) * QKVLD + DIM + h * DHEAD;
    const bf16* Vp = Kp + DIM;

    #pragma unroll
    for (int it = 0; it < 4; it++) {
        int idx = tid + it * 256;
        int r = idx >> 3, c8 = (idx & 7) * 8;
        *(uint4*)&Qs[r * FSH + c8] = *(const uint4*)(Qp + (size_t)r * QKVLD + c8);
    }

    float oacc[8][4] = {};
    float mrun[2] = {-1e30f, -1e30f}, lrun[2] = {0.f, 0.f};
    int rbase = qb * 128 + wid * 16;
    int kmax = 2 * qb + 2;

    for (int kt = 0; kt < kmax; kt++) {
        __syncthreads();
        #pragma unroll
        for (int it = 0; it < 2; it++) {
            int idx = tid + it * 256;
            int r = idx >> 3, c8 = (idx & 7) * 8;
            *(uint4*)&Ks[r * FSH + c8] =
                *(const uint4*)(Kp + (size_t)(kt * 64 + r) * QKVLD + c8);
            uint4 vv = *(const uint4*)(Vp + (size_t)(kt * 64 + r) * QKVLD + c8);
            const bf16* vh = (const bf16*)&vv;
            #pragma unroll
            for (int e = 0; e < 8; e++)
                Vt[(c8 + e) * FSH + r] = vh[e];
        }
        __syncthreads();

        float s[8][4] = {};
        #pragma unroll
        for (int ks = 0; ks < 4; ks++) {
            unsigned aq[4], bk[4][4];
            ldsm4(aq, smQ + ((wid*16 + lrow)*FSH + ks*16 + lk8)*2);
            #pragma unroll
            for (int p = 0; p < 4; p++)
                ldsm4(bk[p], smK + ((p*16 + lrow)*FSH + ks*16 + lk8)*2);
            #pragma unroll
            for (int nt = 0; nt < 8; nt++)
                mma16(s[nt], aq, bk[nt>>1][nt&1], bk[nt>>1][(nt&1)+2]);
        }

        if (kt * 64 + 63 > rbase) {
            int r0 = rbase + g, r1 = r0 + 8;
            #pragma unroll
            for (int nt = 0; nt < 8; nt++) {
                int c0 = kt * 64 + nt * 8 + t * 2;
                if (c0     > r0) s[nt][0] = -1e30f;
                if (c0 + 1 > r0) s[nt][1] = -1e30f;
                if (c0     > r1) s[nt][2] = -1e30f;
                if (c0 + 1 > r1) s[nt][3] = -1e30f;
            }
        }

        #pragma unroll
        for (int r = 0; r < 2; r++) {
            float rm = -1e30f;
            #pragma unroll
            for (int nt = 0; nt < 8; nt++)
                rm = fmaxf(rm, fmaxf(s[nt][2*r], s[nt][2*r + 1]));
            rm = fmaxf(rm, __shfl_xor_sync(0xffffffffu, rm, 1));
            rm = fmaxf(rm, __shfl_xor_sync(0xffffffffu, rm, 2));
            float mn = fmaxf(mrun[r], rm);
            float sc = __expf(mrun[r] - mn);
            float rs = 0.f;
            #pragma unroll
            for (int nt = 0; nt < 8; nt++) {
                s[nt][2*r]     = __expf(s[nt][2*r]     - mn);
                s[nt][2*r + 1] = __expf(s[nt][2*r + 1] - mn);
                rs += s[nt][2*r] + s[nt][2*r + 1];
            }
            rs += __shfl_xor_sync(0xffffffffu, rs, 1);
            rs += __shfl_xor_sync(0xffffffffu, rs, 2);
            lrun[r] = lrun[r] * sc + rs;
            mrun[r] = mn;
            #pragma unroll
            for (int nt = 0; nt < 8; nt++) {
                oacc[nt][2*r]     *= sc;
                oacc[nt][2*r + 1] *= sc;
            }
        }

        #pragma unroll
        for (int nt = 0; nt < 8; nt++) {
            int c = nt * 8 + t * 2;
            *(__nv_bfloat162*)&Ps[(wid*16 + g    ) * FSH + c] = pack_bf2(s[nt][0], s[nt][1]);
            *(__nv_bfloat162*)&Ps[(wid*16 + g + 8) * FSH + c] = pack_bf2(s[nt][2], s[nt][3]);
        }
        __syncwarp();

        #pragma unroll
        for (int ks = 0; ks < 4; ks++) {
            unsigned ap[4], bv[4][4];
            ldsm4(ap, smP + ((wid*16 + lrow)*FSH + ks*16 + lk8)*2);
            #pragma unroll
            for (int p = 0; p < 4; p++)
                ldsm4(bv[p], smV + ((p*16 + lrow)*FSH + ks*16 + lk8)*2);
            #pragma unroll
            for (int nt = 0; nt < 8; nt++)
                mma16(oacc[nt], ap, bv[nt>>1][nt&1], bv[nt>>1][(nt&1)+2]);
        }
    }

    float i0 = 1.f / lrun[0], i1 = 1.f / lrun[1];
    size_t grow0 = (size_t)b * SEQL + qb * 128 + wid * 16 + g;
    #pragma unroll
    for (int nt = 0; nt < 8; nt++) {
        int c = h * DHEAD + nt * 8 + t * 2;
        *(__nv_bfloat162*)&O[grow0 * DIM + c] =
            pack_bf2(oacc[nt][0] * i0, oacc[nt][1] * i0);
        *(__nv_bfloat162*)&O[(grow0 + 8) * DIM + c] =
            pack_bf2(oacc[nt][2] * i1, oacc[nt][3] * i1);
    }
}

// ---------------- host launcher ----------------
typedef CUresult (*tmap_fn_t)(
    CUtensorMap*, CUtensorMapDataType, cuuint32_t, void*,
    const cuuint64_t*, const cuuint64_t*, const cuuint32_t*, const cuuint32_t*,
    CUtensorMapInterleave, CUtensorMapSwizzle, CUtensorMapL2promotion,
    CUtensorMapFloatOOBfill);

static void encode_map(tmap_fn_t fn, CUtensorMap* m, void* p,
                       unsigned long long Kd, unsigned long long Md) {
    cuuint64_t dims[2]    = {Kd, Md};
    cuuint64_t strides[1] = {Kd * 2};
    cuuint32_t box[2]     = {64, 128};
    cuuint32_t es[2]      = {1, 1};
    fn(m, CU_TENSOR_MAP_DATA_TYPE_BFLOAT16, 2, p, dims, strides, box, es,
       CU_TENSOR_MAP_INTERLEAVE_NONE, CU_TENSOR_MAP_SWIZZLE_128B,
       CU_TENSOR_MAP_L2_PROMOTION_L2_128B, CU_TENSOR_MAP_FLOAT_OOB_FILL_NONE);
}

extern "C" void kernel_launch(void* const* d_in, const int* in_sizes, int n_in,
                              void* d_out, int out_size)
{
    const float* x    = (const float*)d_in[0];
    const void*  tmsk = d_in[2];
    const float* Wq   = (const float*)d_in[3];
    const float* Wk   = (const float*)d_in[4];
    const float* Wv   = (const float*)d_in[5];
    const float* Wo   = (const float*)d_in[6];
    const float* w1   = (const float*)d_in[7];
    const float* w2   = (const float*)d_in[8];
    const float* w1t  = (const float*)d_in[9];
    const float* w2t  = (const float*)d_in[10];
    const float* w1s  = (const float*)d_in[11];
    const float* w2s  = (const float*)d_in[12];
    const float* n1w  = (const float*)d_in[13];
    const float* n1b  = (const float*)d_in[14];
    const float* n2w  = (const float*)d_in[15];
    const float* n2b  = (const float*)d_in[16];
    float* out = (float*)d_out;

    bf16 *p_xn, *p_qkv, *p_attn, *p_hcat;
    bf16 *p_wqkv, *p_w1cat, *p_w2cat, *p_woc;
    float *p_x1, *p_pb;
    cudaGetSymbolAddress((void**)&p_xn,    g_xn);
    cudaGetSymbolAddress((void**)&p_qkv,   g_qkv);
    cudaGetSymbolAddress((void**)&p_attn,  g_attn);
    cudaGetSymbolAddress((void**)&p_x1,    g_x1);
    cudaGetSymbolAddress((void**)&p_pb,    g_pb);
    cudaGetSymbolAddress((void**)&p_hcat,  g_hcat);
    cudaGetSymbolAddress((void**)&p_wqkv,  g_wqkv);
    cudaGetSymbolAddress((void**)&p_w1cat, g_w1cat);
    cudaGetSymbolAddress((void**)&p_w2cat, g_w2cat);
    cudaGetSymbolAddress((void**)&p_woc,   g_woc);

    static tmap_fn_t tmap_fn = nullptr;
    static int attr_done = 0;
    if (!attr_done) {
        cudaFuncSetAttribute((const void*)tgemm_tma<1,0,1>, cudaFuncAttributeMaxDynamicSharedMemorySize, TC_SMEM);
        cudaFuncSetAttribute((const void*)tgemm_tma<0,0,0>, cudaFuncAttributeMaxDynamicSharedMemorySize, TC_SMEM);
        cudaFuncSetAttribute((const void*)tgemm_tma<1,1,0>, cudaFuncAttributeMaxDynamicSharedMemorySize, TC_SMEM);
        cudaFuncSetAttribute((const void*)tgemm_down,       cudaFuncAttributeMaxDynamicSharedMemorySize, TC_SMEM);
        cudaFuncSetAttribute((const void*)flash_tc,         cudaFuncAttributeMaxDynamicSharedMemorySize, FA_SMEM);
        cudaDriverEntryPointQueryResult qr;
        cudaGetDriverEntryPoint("cuTensorMapEncodeTiled", (void**)&tmap_fn,
                                cudaEnableDefault, &qr);
        attr_done = 1;
    }

    // tensormaps (encoded on host; captured as kernel params)
    CUtensorMap mXn, mAttn, mHcat, mWqkv, mWoc, mW1, mW2;
    encode_map(tmap_fn, &mXn,   p_xn,    DIM,  NROWS);
    encode_map(tmap_fn, &mAttn, p_attn,  DIM,  NROWS);
    encode_map(tmap_fn, &mHcat, p_hcat,  KCAT, NROWS);
    encode_map(tmap_fn, &mWqkv, p_wqkv,  DIM,  QKVLD);
    encode_map(tmap_fn, &mWoc,  p_woc,   DIM,  DIM);
    encode_map(tmap_fn, &mW1,   p_w1cat, DIM,  KCAT);
    encode_map(tmap_fn, &mW2,   p_w2cat, KCAT, DIM);

    decode_mask_kernel<<<1, 256>>>(tmsk);
    prep_all<<<PREP_QUADS/256, 256>>>(Wq, Wk, Wv, Wo, w1, w1t, w1s, w2, w2t, w2s);

    // ---- attention path ----
    mink_norm_kernel<<<NROWS, 256>>>(x, n1w, n1b, p_xn);

    // QKV with fused Lorentz-qeff epilogue on Q tiles
    tgemm_tma<1,0,1><<<dim3(QKVLD/128, NROWS/128), 256, TC_SMEM>>>(
        mXn, mWqkv, p_qkv, nullptr, DIM, QKVLD, 1.f);

    flash_tc<<<16 * 24, 256, FA_SMEM>>>(p_qkv, p_attn);

    // x1 = x + attn @ Wo^T
    tgemm_tma<0,0,0><<<dim3(DIM/128, NROWS/128), 256, TC_SMEM>>>(
        mAttn, mWoc, p_x1, x, DIM, DIM, 1.f);

    // ---- FFN path ----
    mink_norm_kernel<<<NROWS, 256>>>(p_x1, n2w, n2b, p_xn);

    tgemm_tma<1,1,0><<<dim3(KCAT/128, NROWS/128), 256, TC_SMEM>>>(
        mXn, mW1, p_hcat, nullptr, DIM, KCAT, 1.f);

    // down-projection, split-K=4 (0.5 pre-folded into w2cat)
    tgemm_down<<<dim3(DIM/128, NROWS/128, KSPLIT), 256, TC_SMEM>>>(
        mHcat, mW2, out, p_pb, p_x1);

    // out += pb0 + pb1 + pb2
    addk4<<<NROWS*DIM/4/256, 256>>>(out, p_pb);
}

// round 16
// speedup vs baseline: 1.0634x; 1.0048x over previous
#include <cuda.h>
#include <cuda_runtime.h>
#include <cuda_bf16.h>
#include <math.h>
#include <stdint.h>

typedef __nv_bfloat16 bf16;

// Problem constants
#define BATCH 2
#define SEQL  2048
#define DIM   768
#define NHEAD 12
#define DHEAD 64
#define DFF   3072
#define DFFH  1536
#define NROWS (BATCH*SEQL)          // 4096
#define QKVLD 2304
#define KCAT  6144
#define KSPLIT 4
#define KCHUNK (KCAT/KSPLIT)        // 1536

// ---------------- scratch (static device globals; no allocation) ----------------
__device__ float g_mask [DIM];
__device__ bf16  g_xn   [NROWS*DIM];
__device__ bf16  g_qkv  [(size_t)NROWS*QKVLD];
__device__ bf16  g_attn [NROWS*DIM];
__device__ float g_x1   [NROWS*DIM];
__device__ float g_pb   [(KSPLIT-1)][NROWS*DIM];   // split-K partials (fp32)
__device__ bf16  g_hcat [(size_t)NROWS*KCAT];
__device__ bf16  g_wqkv [QKVLD*DIM];
__device__ bf16  g_w1cat[(size_t)KCAT*DIM];   // mask pre-folded into w1t/w1s rows
__device__ bf16  g_w2cat[(size_t)DIM*KCAT];   // 0.5 blend pre-folded
__device__ bf16  g_woc  [DIM*DIM];

// ---------------- helpers ----------------
__device__ __forceinline__ float gelu_f(float x) {
    return 0.5f * x * (1.f + erff(x * 0.70710678118654752f));
}
__device__ __forceinline__ float silu_f(float x) {
    return x / (1.f + expf(-x));
}
__device__ __forceinline__ __nv_bfloat162 pack_bf2(float a, float b) {
    return __float22bfloat162_rn(make_float2(a, b));
}
__device__ __forceinline__ void mma16(float* c, const unsigned* a,
                                      unsigned b0, unsigned b1) {
    asm volatile(
        "mma.sync.aligned.m16n8k16.row.col.f32.bf16.bf16.f32 "
        "{%0,%1,%2,%3}, {%4,%5,%6,%7}, {%8,%9}, {%0,%1,%2,%3};\n"
        : "+f"(c[0]), "+f"(c[1]), "+f"(c[2]), "+f"(c[3])
        : "r"(a[0]), "r"(a[1]), "r"(a[2]), "r"(a[3]), "r"(b0), "r"(b1));
}
__device__ __forceinline__ void ldsm4(unsigned* r, unsigned addr) {
    asm volatile("ldmatrix.sync.aligned.m8n8.x4.shared.b16 {%0,%1,%2,%3}, [%4];"
        : "=r"(r[0]), "=r"(r[1]), "=r"(r[2]), "=r"(r[3]) : "r"(addr));
}

// ---------------- TMA / mbarrier primitives (sm_90 baseline PTX) ----------------
__device__ __forceinline__ void mbar_init(unsigned a, unsigned cnt) {
    asm volatile("mbarrier.init.shared.b64 [%0], %1;" :: "r"(a), "r"(cnt) : "memory");
}
__device__ __forceinline__ void mbar_expect(unsigned a, unsigned tx) {
    asm volatile("mbarrier.arrive.expect_tx.shared.b64 _, [%0], %1;"
                 :: "r"(a), "r"(tx) : "memory");
}
__device__ __forceinline__ void mbar_arrive(unsigned a) {
    asm volatile("mbarrier.arrive.release.cta.shared::cta.b64 _, [%0];"
                 :: "r"(a) : "memory");
}
__device__ __forceinline__ void mbar_wait(unsigned a, unsigned parity) {
    asm volatile(
        "{\n\t.reg .pred P;\n"
        "W%=:\n\t"
        "mbarrier.try_wait.parity.acquire.cta.shared::cta.b64 P, [%0], %1;\n\t"
        "@!P bra W%=;\n\t}"
        :: "r"(a), "r"(parity) : "memory");
}
__device__ __forceinline__ void tma2d(unsigned dst, const CUtensorMap* m,
                                      int x, int y, unsigned bar) {
    asm volatile(
        "cp.async.bulk.tensor.2d.shared::cta.global.tile.mbarrier::complete_tx::bytes "
        "[%0], [%1, {%2, %3}], [%4];"
        :: "r"(dst), "l"(m), "r"(x), "r"(y), "r"(bar) : "memory");
}

// ---------------- timelike_mask decode (dtype-robust: f32 / i32 / bool8) ----------------
__global__ void decode_mask_kernel(const void* __restrict__ raw) {
    __shared__ int cls;
    if (threadIdx.x == 0) {
        const unsigned* w = (const unsigned*)raw;
        int isFloat = 0, isByte = 0;
        for (int i = 0; i < 192; i++) {
            unsigned v = w[i];
            if (v == 0x3F800000u) isFloat = 1;
            if (v != 0u) {
                bool bytes01 = true, hi = false;
                for (int b = 0; b < 4; b++) {
                    unsigned by = (v >> (8*b)) & 0xffu;
                    if (by > 1u) bytes01 = false;
                    if (b > 0 && by) hi = true;
                }
                if (bytes01 && hi) isByte = 1;
            }
        }
        cls = isFloat ? 0 : (isByte ? 2 : 1);
    }
    __syncthreads();
    int c = cls;
    for (int i = threadIdx.x; i < DIM; i += blockDim.x) {
        float mv;
        if (c == 0)      mv = ((const float*)raw)[i];
        else if (c == 1) mv = (float)(((const int*)raw)[i] != 0);
        else             mv = (float)(((const unsigned char*)raw)[i] != 0);
        g_mask[i] = mv;
    }
}

// ---------------- fused weight prep: concat + bf16 + mask/scale folding ----------------
#define PR_S0 (QKVLD*DIM)
#define PR_S1 (PR_S0 + (size_t)KCAT*DIM)
#define PR_S2 (PR_S1 + (size_t)DIM*KCAT)
#define PR_S3 (PR_S2 + (size_t)DIM*DIM)
#define PREP_QUADS (PR_S3/4)

__global__ __launch_bounds__(256) void prep_all(
    const float* __restrict__ Wq, const float* __restrict__ Wk,
    const float* __restrict__ Wv, const float* __restrict__ Wo,
    const float* __restrict__ w1, const float* __restrict__ w1t,
    const float* __restrict__ w1s, const float* __restrict__ w2,
    const float* __restrict__ w2t, const float* __restrict__ w2s)
{
    size_t i = (size_t)(blockIdx.x * 256 + threadIdx.x) * 4;
    const float* src;
    bf16* dst;
    float m0 = 1.f, m1 = 1.f, m2 = 1.f, m3 = 1.f;
    if (i < PR_S0) {
        int r = (int)(i / DIM), c = (int)(i % DIM);
        src = (r < DIM) ? (Wq + (size_t)r*DIM + c)
            : (r < 2*DIM) ? (Wk + (size_t)(r-DIM)*DIM + c)
            : (Wv + (size_t)(r-2*DIM)*DIM + c);
        dst = g_wqkv + i;
    } else if (i < PR_S1) {
        size_t j = i - PR_S0;
        int r = (int)(j / DIM), c = (int)(j % DIM);
        if (r < DFF) {
            src = w1 + (size_t)r*DIM + c;
        } else if (r < DFF + DFFH) {
            src = w1t + (size_t)(r-DFF)*DIM + c;
            m0 = g_mask[c]; m1 = g_mask[c+1]; m2 = g_mask[c+2]; m3 = g_mask[c+3];
        } else {
            src = w1s + (size_t)(r-DFF-DFFH)*DIM + c;
            m0 = 1.f-g_mask[c]; m1 = 1.f-g_mask[c+1];
            m2 = 1.f-g_mask[c+2]; m3 = 1.f-g_mask[c+3];
        }
        dst = g_w1cat + j;
    } else if (i < PR_S2) {
        size_t j = i - PR_S1;
        int r = (int)(j / KCAT), c = (int)(j % KCAT);
        src = (c < DFF) ? (w2 + (size_t)r*DFF + c)
            : (c < DFF+DFFH) ? (w2t + (size_t)r*DFFH + c - DFF)
            : (w2s + (size_t)r*DFFH + c - DFF - DFFH);
        dst = g_w2cat + j;
        m0 = m1 = m2 = m3 = 0.5f;                 // fold FFN blend scale
    } else {
        size_t j = i - PR_S2;
        src = Wo + j;
        dst = g_woc + j;
    }
    float4 v = *(const float4*)src;
    *(__nv_bfloat162*)dst       = pack_bf2(v.x * m0, v.y * m1);
    *(__nv_bfloat162*)(dst + 2) = pack_bf2(v.z * m2, v.w * m3);
}

// ---------------- Minkowski LayerNorm (bf16 output) ----------------
__global__ __launch_bounds__(256) void mink_norm_kernel(
    const float* __restrict__ x, const float* __restrict__ w,
    const float* __restrict__ bb, bf16* __restrict__ out)
{
    __shared__ float sA[8], sB[8];
    int row = blockIdx.x, t = threadIdx.x;
    const float* xr = x + (size_t)row * DIM;
    float v0 = xr[t], v1 = xr[t+256], v2 = xr[t+512];
    int lane = t & 31, wp = t >> 5;

    float s = v0 + v1 + v2;
    #pragma unroll
    for (int o = 16; o; o >>= 1) s += __shfl_xor_sync(0xffffffffu, s, o);
    if (!lane) sA[wp] = s;
    __syncthreads();
    float tot = 0.f;
    #pragma unroll
    for (int i = 0; i < 8; i++) tot += sA[i];
    float mean = tot * (1.f / DIM);

    float c0 = v0 - mean, c1 = v1 - mean, c2 = v2 - mean;
    float m0 = g_mask[t], m1 = g_mask[t+256], m2 = g_mask[t+512];
    float s2  = c0*c0 + c1*c1 + c2*c2;
    float s2m = c0*c0*m0 + c1*c1*m1 + c2*c2*m2;
    #pragma unroll
    for (int o = 16; o; o >>= 1) {
        s2  += __shfl_xor_sync(0xffffffffu, s2,  o);
        s2m += __shfl_xor_sync(0xffffffffu, s2m, o);
    }
    __syncthreads();
    if (!lane) { sA[wp] = s2; sB[wp] = s2m; }
    __syncthreads();
    float S2 = 0.f, S2m = 0.f;
    #pragma unroll
    for (int i = 0; i < 8; i++) { S2 += sA[i]; S2m += sB[i]; }

    float var = S2 * (1.f / DIM);
    float eta = S2 - 2.f * S2m;
    float kk  = 0.5f * (rsqrtf(var + 1e-5f) + rsqrtf(fabsf(eta) + 1e-5f));

    size_t o0 = (size_t)row * DIM + t;
    out[o0]     = __float2bfloat16_rn(w[t]     * (c0 * kk) + bb[t]);
    out[o0+256] = __float2bfloat16_rn(w[t+256] * (c1 * kk) + bb[t+256]);
    out[o0+512] = __float2bfloat16_rn(w[t+512] * (c2 * kk) + bb[t+512]);
}

// ---------------- TMA-fed bf16 tensor-core NT GEMM ----------------
// 3-stage ring; per-stage full (TMA tx) + empty (8 warp arrivals) mbarriers.
// No __syncthreads in the mainloop: consumer warps free-run, only thread 0
// (the TMA producer) waits on the empty barrier before refilling a buffer.
#define TSTG 3
#define TSTB 32768
#define TC_SMEM (TSTG*TSTB + 1024)

__device__ __forceinline__ void gemm_tma_core(
    const CUtensorMap& mapA, const CUtensorMap& mapB,
    int k0, int nk, int bm, int bn, float (&acc)[4][4][4])
{
    extern __shared__ char tsm[];
    uintptr_t gp = (uintptr_t)tsm;
    unsigned base = (unsigned)__cvta_generic_to_shared(
        (void*)((gp + 1023) & ~(uintptr_t)1023));
    __shared__ __align__(8) unsigned long long mbar_s[2*TSTG];
    unsigned mbF = (unsigned)__cvta_generic_to_shared(mbar_s);
    unsigned mbE = mbF + 8*TSTG;

    int tid = threadIdx.x, lane = tid & 31, wid = tid >> 5;
    int wm = wid & 1, wn = wid >> 1;
    int lrow = lane & 15, lu = lane >> 4;

    if (tid == 0) {
        #pragma unroll
        for (int s = 0; s < TSTG; s++) {
            mbar_init(mbF + 8*s, 1);
            mbar_init(mbE + 8*s, 8);     // one arrival per warp
        }
    }
    __syncthreads();
    if (tid == 0) {
        for (int s = 0; s < TSTG && s < nk; s++) {
            mbar_expect(mbF + 8*s, TSTB);
            tma2d(base + s*TSTB,         &mapA, k0 + s*64, bm, mbF + 8*s);
            tma2d(base + s*TSTB + 16384, &mapB, k0 + s*64, bn, mbF + 8*s);
        }
    }

    for (int kt = 0; kt < nk; kt++) {
        int b = kt % TSTG;
        unsigned par = (unsigned)((kt / TSTG) & 1);
        mbar_wait(mbF + 8*b, par);
        unsigned stA = base + b*TSTB, stB = stA + 16384;
        #pragma unroll
        for (int ks = 0; ks < 4; ks++) {
            unsigned af[4][4], bq[2][4];
            #pragma unroll
            for (int mt = 0; mt < 4; mt++) {
                int r = wm*64 + mt*16 + lrow;
                ldsm4(af[mt], stA + r*128 + ((((ks<<1)|lu) ^ (r&7)) << 4));
            }
            #pragma unroll
            for (int p = 0; p < 2; p++) {
                int r = wn*32 + p*16 + lrow;
                ldsm4(bq[p], stB + r*128 + ((((ks<<1)|lu) ^ (r&7)) << 4));
            }
            #pragma unroll
            for (int mt = 0; mt < 4; mt++)
                #pragma unroll
                for (int nt = 0; nt < 4; nt++)
                    mma16(acc[mt][nt], af[mt],
                          bq[nt>>1][nt&1], bq[nt>>1][(nt&1)+2]);
        }
        if (lane == 0) mbar_arrive(mbE + 8*b);   // this warp done reading stage
        if (tid == 0 && kt + TSTG < nk) {
            mbar_wait(mbE + 8*b, par);           // all 8 warps done with buffer b
            asm volatile("fence.proxy.async.shared::cta;" ::: "memory");
            mbar_expect(mbF + 8*b, TSTB);
            tma2d(stA, &mapA, k0 + (kt + TSTG)*64, bm, mbF + 8*b);
            tma2d(stB, &mapB, k0 + (kt + TSTG)*64, bn, mbF + 8*b);
        }
    }
}

// epilogue: OT 0 fp32(+resid, alpha), 1 bf16 (act), 2 raw fp32 partial
template<int OT>
__device__ __forceinline__ void store_epi4(
    float (&acc)[4][4][4], void* Cv, const float* __restrict__ resid,
    int ldc, float alpha, int bm, int bn, int act)
{
    int tid = threadIdx.x, lane = tid & 31, wid = tid >> 5;
    int wm = wid & 1, wn = wid >> 1;
    int g = lane >> 2, t = lane & 3;
    #pragma unroll
    for (int mt = 0; mt < 4; mt++) {
        int r0 = bm + wm*64 + mt*16 + g;
        #pragma unroll
        for (int nt = 0; nt < 4; nt++) {
            int c = bn + wn*32 + nt*8 + t*2;
            #pragma unroll
            for (int hh = 0; hh < 2; hh++) {
                float v0 = acc[mt][nt][2*hh];
                float v1 = acc[mt][nt][2*hh + 1];
                size_t idx = (size_t)(r0 + 8*hh) * ldc + c;
                if (OT == 1) {
                    if (act == 1) { v0 = gelu_f(v0); v1 = gelu_f(v1); }
                    else if (act == 2) { v0 = silu_f(v0); v1 = silu_f(v1); }
                    *(__nv_bfloat162*)((bf16*)Cv + idx) = pack_bf2(v0, v1);
                } else if (OT == 0) {
                    v0 *= alpha; v1 *= alpha;
                    if (resid) {
                        float2 rv = *(const float2*)(resid + idx);
                        v0 += rv.x; v1 += rv.y;
                    }
                    *(float2*)((float*)Cv + idx) = make_float2(v0, v1);
                } else {
                    *(float2*)((float*)Cv + idx) = make_float2(v0, v1);
                }
            }
        }
    }
}

// fused Lorentz-qeff epilogue for Q tiles (bn < DIM)
__device__ void store_epi_qeff(
    float (&acc)[4][4][4], bf16* __restrict__ C, int ldc, int bm, int bn)
{
    extern __shared__ char tsm[];
    float* sred = (float*)tsm;                 // [8 warps][64 rows][2]
    int tid = threadIdx.x, lane = tid & 31, wid = tid >> 5;
    int wm = wid & 1, wn = wid >> 1;
    int g = lane >> 2, t = lane & 3;
    int pw = wid ^ 2;                          // partner warp: same wm, wn^1

    float mcol[4][2];
    #pragma unroll
    for (int nt = 0; nt < 4; nt++) {
        int c = bn + wn*32 + nt*8 + t*2;
        mcol[nt][0] = g_mask[c];
        mcol[nt][1] = g_mask[c + 1];
    }

    float qn[8], qt[8];
    #pragma unroll
    for (int mt = 0; mt < 4; mt++)
        #pragma unroll
        for (int hh = 0; hh < 2; hh++) {
            float a = 0.f, b = 0.f;
            #pragma unroll
            for (int nt = 0; nt < 4; nt++) {
                float v0 = acc[mt][nt][2*hh], v1 = acc[mt][nt][2*hh + 1];
                a += v0*v0 + v1*v1;
                b += v0*v0*mcol[nt][0] + v1*v1*mcol[nt][1];
            }
            a += __shfl_xor_sync(0xffffffffu, a, 1);
            b += __shfl_xor_sync(0xffffffffu, b, 1);
            a += __shfl_xor_sync(0xffffffffu, a, 2);
            b += __shfl_xor_sync(0xffffffffu, b, 2);
            qn[mt*2 + hh] = a; qt[mt*2 + hh] = b;
        }

    __syncthreads();       // all warps past mainloop; smem ring reusable
    if (t == 0) {
        #pragma unroll
        for (int i = 0; i < 8; i++) {
            int row = (i >> 1) * 16 + g + 8 * (i & 1);
            sred[(wid*64 + row)*2 + 0] = qn[i];
            sred[(wid*64 + row)*2 + 1] = qt[i];
        }
    }
    __syncthreads();

    #pragma unroll
    for (int mt = 0; mt < 4; mt++)
        #pragma unroll
        for (int hh = 0; hh < 2; hh++) {
            int row = mt*16 + g + 8*hh;
            float a = qn[mt*2 + hh] + sred[(pw*64 + row)*2 + 0];
            float b = qt[mt*2 + hh] + sred[(pw*64 + row)*2 + 1];
            float qtn = sqrtf(b);
            float sf = (qtn > 1e-6f) ? sqrtf(a) / fmaxf(qtn, 1e-8f) : 0.f;
            int r0 = bm + wm*64 + row;
            #pragma unroll
            for (int nt = 0; nt < 4; nt++) {
                int c = bn + wn*32 + nt*8 + t*2;
                float v0 = acc[mt][nt][2*hh]   * (1.f - 0.5f*sf*mcol[nt][0]) * 0.125f;
                float v1 = acc[mt][nt][2*hh+1] * (1.f - 0.5f*sf*mcol[nt][1]) * 0.125f;
                *(__nv_bfloat162*)(C + (size_t)r0*ldc + c) = pack_bf2(v0, v1);
            }
        }
}

template<int OT, int ACTSEL, int QEFF>
__global__ __launch_bounds__(256, 2) void tgemm_tma(
    const __grid_constant__ CUtensorMap mapA,
    const __grid_constant__ CUtensorMap mapB,
    void* __restrict__ C, const float* __restrict__ resid,
    int K, int ldc, float alpha)
{
    int bm = blockIdx.y * 128, bn = blockIdx.x * 128;
    float acc[4][4][4] = {};
    gemm_tma_core(mapA, mapB, 0, K >> 6, bm, bn, acc);
    if (QEFF && bn < DIM) {
        store_epi_qeff(acc, (bf16*)C, ldc, bm, bn);
    } else {
        int act = ACTSEL ? ((bn >= DFF && bn < DFF + DFFH) ? 2 : 1) : 0;
        store_epi4<OT>(acc, C, resid, ldc, alpha, bm, bn, act);
    }
}

// split-K down-projection (0.5 pre-folded into w2cat):
// z=0 -> out = x1 + chunk0 ; z>=1 -> pb[z-1] = chunk_z (raw fp32)
__global__ __launch_bounds__(256, 2) void tgemm_down(
    const __grid_constant__ CUtensorMap mapA,
    const __grid_constant__ CUtensorMap mapB,
    float* __restrict__ out, float* __restrict__ pb0,
    const float* __restrict__ resid)
{
    int bm = blockIdx.y * 128, bn = blockIdx.x * 128;
    int z = blockIdx.z;
    float acc[4][4][4] = {};
    gemm_tma_core(mapA, mapB, z * KCHUNK, KCHUNK >> 6, bm, bn, acc);
    if (z == 0) store_epi4<0>(acc, out, resid, DIM, 1.f, bm, bn, 0);
    else        store_epi4<2>(acc, pb0 + (size_t)(z-1)*NROWS*DIM, nullptr,
                              DIM, 0.f, bm, bn, 0);
}

// final: out += pb0 + pb1 + pb2  (scales pre-folded)
__global__ __launch_bounds__(256) void addk4(
    float* __restrict__ out, const float* __restrict__ pb)
{
    int i = blockIdx.x * 256 + threadIdx.x;
    float4 o  = ((const float4*)out)[i];
    float4 p0 = ((const float4*)(pb))[i];
    float4 p1 = ((const float4*)(pb + (size_t)NROWS*DIM))[i];
    float4 p2 = ((const float4*)(pb + (size_t)2*NROWS*DIM))[i];
    ((float4*)out)[i] = make_float4(o.x + p0.x + p1.x + p2.x,
                                    o.y + p0.y + p1.y + p2.y,
                                    o.z + p0.z + p1.z + p2.z,
                                    o.w + p0.w + p1.w + p2.w);
}

// ---------------- bf16 tensor-core causal flash attention ----------------
#define FSH 72
#define FA_SMEM ((128 + 64 + 64 + 128) * FSH * 2)   // 55296 bytes

__global__ __launch_bounds__(256) void flash_tc(
    const bf16* __restrict__ QKV, bf16* __restrict__ O)
{
    extern __shared__ char smc[];
    bf16* Qs = (bf16*)smc;
    bf16* Ks = Qs + 128 * FSH;
    bf16* Vt = Qs + 192 * FSH;
    bf16* Ps = Qs + 256 * FSH;
    unsigned smQ = (unsigned)__cvta_generic_to_shared(Qs);
    unsigned smK = smQ + 128 * FSH * 2;
    unsigned smV = smQ + 192 * FSH * 2;
    unsigned smP = smQ + 256 * FSH * 2;

    int tid = threadIdx.x, lane = tid & 31, wid = tid >> 5;
    int g = lane >> 2, t = lane & 3;
    int lrow = lane & 15, lk8 = (lane >> 4) << 3;
    int bid = blockIdx.x;
    int qb = 15 - bid / 24;
    int bh = bid % 24;
    int b = bh / NHEAD, h = bh % NHEAD;

    const bf16* Qp = QKV + (size_t)(b * SEQL + qb * 128) * QKVLD + h * DHEAD;
    const bf16* Kp = QKV + (size_t)(b * SEQL) * QKVLD + DIM + h * DHEAD;
    const bf16* Vp = Kp + DIM;

    #pragma unroll
    for (int it = 0; it < 4; it++) {
        int idx = tid + it * 256;
        int r = idx >> 3, c8 = (idx & 7) * 8;
        *(uint4*)&Qs[r * FSH + c8] = *(const uint4*)(Qp + (size_t)r * QKVLD + c8);
    }

    float oacc[8][4] = {};
    float mrun[2] = {-1e30f, -1e30f}, lrun[2] = {0.f, 0.f};
    int rbase = qb * 128 + wid * 16;
    int kmax = 2 * qb + 2;

    for (int kt = 0; kt < kmax; kt++) {
        __syncthreads();
        #pragma unroll
        for (int it = 0; it < 2; it++) {
            int idx = tid + it * 256;
            int r = idx >> 3, c8 = (idx & 7) * 8;
            *(uint4*)&Ks[r * FSH + c8] =
                *(const uint4*)(Kp + (size_t)(kt * 64 + r) * QKVLD + c8);
            uint4 vv = *(const uint4*)(Vp + (size_t)(kt * 64 + r) * QKVLD + c8);
            const bf16* vh = (const bf16*)&vv;
            #pragma unroll
            for (int e = 0; e < 8; e++)
                Vt[(c8 + e) * FSH + r] = vh[e];
        }
        __syncthreads();

        float s[8][4] = {};
        #pragma unroll
        for (int ks = 0; ks < 4; ks++) {
            unsigned aq[4], bk[4][4];
            ldsm4(aq, smQ + ((wid*16 + lrow)*FSH + ks*16 + lk8)*2);
            #pragma unroll
            for (int p = 0; p < 4; p++)
                ldsm4(bk[p], smK + ((p*16 + lrow)*FSH + ks*16 + lk8)*2);
            #pragma unroll
            for (int nt = 0; nt < 8; nt++)
                mma16(s[nt], aq, bk[nt>>1][nt&1], bk[nt>>1][(nt&1)+2]);
        }

        if (kt * 64 + 63 > rbase) {
            int r0 = rbase + g, r1 = r0 + 8;
            #pragma unroll
            for (int nt = 0; nt < 8; nt++) {
                int c0 = kt * 64 + nt * 8 + t * 2;
                if (c0     > r0) s[nt][0] = -1e30f;
                if (c0 + 1 > r0) s[nt][1] = -1e30f;
                if (c0     > r1) s[nt][2] = -1e30f;
                if (c0 + 1 > r1) s[nt][3] = -1e30f;
            }
        }

        #pragma unroll
        for (int r = 0; r < 2; r++) {
            float rm = -1e30f;
            #pragma unroll
            for (int nt = 0; nt < 8; nt++)
                rm = fmaxf(rm, fmaxf(s[nt][2*r], s[nt][2*r + 1]));
            rm = fmaxf(rm, __shfl_xor_sync(0xffffffffu, rm, 1));
            rm = fmaxf(rm, __shfl_xor_sync(0xffffffffu, rm, 2));
            float mn = fmaxf(mrun[r], rm);
            float sc = __expf(mrun[r] - mn);
            float rs = 0.f;
            #pragma unroll
            for (int nt = 0; nt < 8; nt++) {
                s[nt][2*r]     = __expf(s[nt][2*r]     - mn);
                s[nt][2*r + 1] = __expf(s[nt][2*r + 1] - mn);
                rs += s[nt][2*r] + s[nt][2*r + 1];
            }
            rs += __shfl_xor_sync(0xffffffffu, rs, 1);
            rs += __shfl_xor_sync(0xffffffffu, rs, 2);
            lrun[r] = lrun[r] * sc + rs;
            mrun[r] = mn;
            #pragma unroll
            for (int nt = 0; nt < 8; nt++) {
                oacc[nt][2*r]     *= sc;
                oacc[nt][2*r + 1] *= sc;
            }
        }

        #pragma unroll
        for (int nt = 0; nt < 8; nt++) {
            int c = nt * 8 + t * 2;
            *(__nv_bfloat162*)&Ps[(wid*16 + g    ) * FSH + c] = pack_bf2(s[nt][0], s[nt][1]);
            *(__nv_bfloat162*)&Ps[(wid*16 + g + 8) * FSH + c] = pack_bf2(s[nt][2], s[nt][3]);
        }
        __syncwarp();

        #pragma unroll
        for (int ks = 0; ks < 4; ks++) {
            unsigned ap[4], bv[4][4];
            ldsm4(ap, smP + ((wid*16 + lrow)*FSH + ks*16 + lk8)*2);
            #pragma unroll
            for (int p = 0; p < 4; p++)
                ldsm4(bv[p], smV + ((p*16 + lrow)*FSH + ks*16 + lk8)*2);
            #pragma unroll
            for (int nt = 0; nt < 8; nt++)
                mma16(oacc[nt], ap, bv[nt>>1][nt&1], bv[nt>>1][(nt&1)+2]);
        }
    }

    float i0 = 1.f / lrun[0], i1 = 1.f / lrun[1];
    size_t grow0 = (size_t)b * SEQL + qb * 128 + wid * 16 + g;
    #pragma unroll
    for (int nt = 0; nt < 8; nt++) {
        int c = h * DHEAD + nt * 8 + t * 2;
        *(__nv_bfloat162*)&O[grow0 * DIM + c] =
            pack_bf2(oacc[nt][0] * i0, oacc[nt][1] * i0);
        *(__nv_bfloat162*)&O[(grow0 + 8) * DIM + c] =
            pack_bf2(oacc[nt][2] * i1, oacc[nt][3] * i1);
    }
}

// ---------------- host launcher ----------------
typedef CUresult (*tmap_fn_t)(
    CUtensorMap*, CUtensorMapDataType, cuuint32_t, void*,
    const cuuint64_t*, const cuuint64_t*, const cuuint32_t*, const cuuint32_t*,
    CUtensorMapInterleave, CUtensorMapSwizzle, CUtensorMapL2promotion,
    CUtensorMapFloatOOBfill);

static void encode_map(tmap_fn_t fn, CUtensorMap* m, void* p,
                       unsigned long long Kd, unsigned long long Md) {
    cuuint64_t dims[2]    = {Kd, Md};
    cuuint64_t strides[1] = {Kd * 2};
    cuuint32_t box[2]     = {64, 128};
    cuuint32_t es[2]      = {1, 1};
    fn(m, CU_TENSOR_MAP_DATA_TYPE_BFLOAT16, 2, p, dims, strides, box, es,
       CU_TENSOR_MAP_INTERLEAVE_NONE, CU_TENSOR_MAP_SWIZZLE_128B,
       CU_TENSOR_MAP_L2_PROMOTION_L2_128B, CU_TENSOR_MAP_FLOAT_OOB_FILL_NONE);
}

extern "C" void kernel_launch(void* const* d_in, const int* in_sizes, int n_in,
                              void* d_out, int out_size)
{
    const float* x    = (const float*)d_in[0];
    const void*  tmsk = d_in[2];
    const float* Wq   = (const float*)d_in[3];
    const float* Wk   = (const float*)d_in[4];
    const float* Wv   = (const float*)d_in[5];
    const float* Wo   = (const float*)d_in[6];
    const float* w1   = (const float*)d_in[7];
    const float* w2   = (const float*)d_in[8];
    const float* w1t  = (const float*)d_in[9];
    const float* w2t  = (const float*)d_in[10];
    const float* w1s  = (const float*)d_in[11];
    const float* w2s  = (const float*)d_in[12];
    const float* n1w  = (const float*)d_in[13];
    const float* n1b  = (const float*)d_in[14];
    const float* n2w  = (const float*)d_in[15];
    const float* n2b  = (const float*)d_in[16];
    float* out = (float*)d_out;

    bf16 *p_xn, *p_qkv, *p_attn, *p_hcat;
    bf16 *p_wqkv, *p_w1cat, *p_w2cat, *p_woc;
    float *p_x1, *p_pb;
    cudaGetSymbolAddress((void**)&p_xn,    g_xn);
    cudaGetSymbolAddress((void**)&p_qkv,   g_qkv);
    cudaGetSymbolAddress((void**)&p_attn,  g_attn);
    cudaGetSymbolAddress((void**)&p_x1,    g_x1);
    cudaGetSymbolAddress((void**)&p_pb,    g_pb);
    cudaGetSymbolAddress((void**)&p_hcat,  g_hcat);
    cudaGetSymbolAddress((void**)&p_wqkv,  g_wqkv);
    cudaGetSymbolAddress((void**)&p_w1cat, g_w1cat);
    cudaGetSymbolAddress((void**)&p_w2cat, g_w2cat);
    cudaGetSymbolAddress((void**)&p_woc,   g_woc);

    static tmap_fn_t tmap_fn = nullptr;
    static int attr_done = 0;
    if (!attr_done) {
        cudaFuncSetAttribute((const void*)tgemm_tma<1,0,1>, cudaFuncAttributeMaxDynamicSharedMemorySize, TC_SMEM);
        cudaFuncSetAttribute((const void*)tgemm_tma<0,0,0>, cudaFuncAttributeMaxDynamicSharedMemorySize, TC_SMEM);
        cudaFuncSetAttribute((const void*)tgemm_tma<1,1,0>, cudaFuncAttributeMaxDynamicSharedMemorySize, TC_SMEM);
        cudaFuncSetAttribute((const void*)tgemm_down,       cudaFuncAttributeMaxDynamicSharedMemorySize, TC_SMEM);
        cudaFuncSetAttribute((const void*)flash_tc,         cudaFuncAttributeMaxDynamicSharedMemorySize, FA_SMEM);
        cudaDriverEntryPointQueryResult qr;
        cudaGetDriverEntryPoint("cuTensorMapEncodeTiled", (void**)&tmap_fn,
                                cudaEnableDefault, &qr);
        attr_done = 1;
    }

    // tensormaps (encoded on host; captured as kernel params)
    CUtensorMap mXn, mAttn, mHcat, mWqkv, mWoc, mW1, mW2;
    encode_map(tmap_fn, &mXn,   p_xn,    DIM,  NROWS);
    encode_map(tmap_fn, &mAttn, p_attn,  DIM,  NROWS);
    encode_map(tmap_fn, &mHcat, p_hcat,  KCAT, NROWS);
    encode_map(tmap_fn, &mWqkv, p_wqkv,  DIM,  QKVLD);
    encode_map(tmap_fn, &mWoc,  p_woc,   DIM,  DIM);
    encode_map(tmap_fn, &mW1,   p_w1cat, DIM,  KCAT);
    encode_map(tmap_fn, &mW2,   p_w2cat, KCAT, DIM);

    decode_mask_kernel<<<1, 256>>>(tmsk);
    prep_all<<<PREP_QUADS/256, 256>>>(Wq, Wk, Wv, Wo, w1, w1t, w1s, w2, w2t, w2s);

    // ---- attention path ----
    mink_norm_kernel<<<NROWS, 256>>>(x, n1w, n1b, p_xn);

    // QKV with fused Lorentz-qeff epilogue on Q tiles
    tgemm_tma<1,0,1><<<dim3(QKVLD/128, NROWS/128), 256, TC_SMEM>>>(
        mXn, mWqkv, p_qkv, nullptr, DIM, QKVLD, 1.f);

    flash_tc<<<16 * 24, 256, FA_SMEM>>>(p_qkv, p_attn);

    // x1 = x + attn @ Wo^T
    tgemm_tma<0,0,0><<<dim3(DIM/128, NROWS/128), 256, TC_SMEM>>>(
        mAttn, mWoc, p_x1, x, DIM, DIM, 1.f);

    // ---- FFN path ----
    mink_norm_kernel<<<NROWS, 256>>>(p_x1, n2w, n2b, p_xn);

    tgemm_tma<1,1,0><<<dim3(KCAT/128, NROWS/128), 256, TC_SMEM>>>(
        mXn, mW1, p_hcat, nullptr, DIM, KCAT, 1.f);

    // down-projection, split-K=4 (0.5 pre-folded into w2cat)
    tgemm_down<<<dim3(DIM/128, NROWS/128, KSPLIT), 256, TC_SMEM>>>(
        mHcat, mW2, out, p_pb, p_x1);

    // out += pb0 + pb1 + pb2
    addk4<<<NROWS*DIM/4/256, 256>>>(out, p_pb);
}

// round 17
// speedup vs baseline: 1.1372x; 1.0694x over previous
#include <cuda.h>
#include <cuda_runtime.h>
#include <cuda_bf16.h>
#include <math.h>
#include <stdint.h>

typedef __nv_bfloat16 bf16;

// Problem constants
#define BATCH 2
#define SEQL  2048
#define DIM   768
#define NHEAD 12
#define DHEAD 64
#define DFF   3072
#define DFFH  1536
#define NROWS (BATCH*SEQL)          // 4096
#define QKVLD 2304
#define KCAT  6144
#define KSPLIT 4
#define KCHUNK (KCAT/KSPLIT)        // 1536

// ---------------- scratch (static device globals; no allocation) ----------------
__device__ float g_mask [DIM];
__device__ bf16  g_xn   [NROWS*DIM];
__device__ bf16  g_qkv  [(size_t)NROWS*QKVLD];
__device__ bf16  g_attn [NROWS*DIM];
__device__ float g_x1   [NROWS*DIM];
__device__ float g_pb   [(KSPLIT-1)][NROWS*DIM];   // split-K partials (fp32)
__device__ bf16  g_hcat [(size_t)NROWS*KCAT];
__device__ bf16  g_wqkv [QKVLD*DIM];
__device__ bf16  g_w1cat[(size_t)KCAT*DIM];   // mask pre-folded into w1t/w1s rows
__device__ bf16  g_w2cat[(size_t)DIM*KCAT];   // 0.5 blend pre-folded
__device__ bf16  g_woc  [DIM*DIM];

// ---------------- helpers ----------------
__device__ __forceinline__ float gelu_f(float x) {
    return 0.5f * x * (1.f + erff(x * 0.70710678118654752f));
}
__device__ __forceinline__ float silu_f(float x) {
    return x / (1.f + expf(-x));
}
__device__ __forceinline__ __nv_bfloat162 pack_bf2(float a, float b) {
    return __float22bfloat162_rn(make_float2(a, b));
}
__device__ __forceinline__ void mma16(float* c, const unsigned* a,
                                      unsigned b0, unsigned b1) {
    asm volatile(
        "mma.sync.aligned.m16n8k16.row.col.f32.bf16.bf16.f32 "
        "{%0,%1,%2,%3}, {%4,%5,%6,%7}, {%8,%9}, {%0,%1,%2,%3};\n"
        : "+f"(c[0]), "+f"(c[1]), "+f"(c[2]), "+f"(c[3])
        : "r"(a[0]), "r"(a[1]), "r"(a[2]), "r"(a[3]), "r"(b0), "r"(b1));
}
__device__ __forceinline__ void ldsm4(unsigned* r, unsigned addr) {
    asm volatile("ldmatrix.sync.aligned.m8n8.x4.shared.b16 {%0,%1,%2,%3}, [%4];"
        : "=r"(r[0]), "=r"(r[1]), "=r"(r[2]), "=r"(r[3]) : "r"(addr));
}
__device__ __forceinline__ void ldsm4t(unsigned* r, unsigned addr) {
    asm volatile("ldmatrix.sync.aligned.m8n8.x4.trans.shared.b16 {%0,%1,%2,%3}, [%4];"
        : "=r"(r[0]), "=r"(r[1]), "=r"(r[2]), "=r"(r[3]) : "r"(addr));
}
__device__ __forceinline__ void cp16(unsigned dst, const void* src) {
    asm volatile("cp.async.cg.shared.global [%0], [%1], 16;\n" :: "r"(dst), "l"(src));
}
__device__ __forceinline__ void cp_commit() { asm volatile("cp.async.commit_group;\n"); }
template<int N> __device__ __forceinline__ void cp_wait() {
    asm volatile("cp.async.wait_group %0;\n" :: "n"(N));
}

// ---------------- TMA / mbarrier primitives (sm_90 baseline PTX) ----------------
__device__ __forceinline__ void mbar_init(unsigned a, unsigned cnt) {
    asm volatile("mbarrier.init.shared.b64 [%0], %1;" :: "r"(a), "r"(cnt) : "memory");
}
__device__ __forceinline__ void mbar_expect(unsigned a, unsigned tx) {
    asm volatile("mbarrier.arrive.expect_tx.shared.b64 _, [%0], %1;"
                 :: "r"(a), "r"(tx) : "memory");
}
__device__ __forceinline__ void mbar_arrive(unsigned a) {
    asm volatile("mbarrier.arrive.release.cta.shared::cta.b64 _, [%0];"
                 :: "r"(a) : "memory");
}
__device__ __forceinline__ void mbar_wait(unsigned a, unsigned parity) {
    asm volatile(
        "{\n\t.reg .pred P;\n"
        "W%=:\n\t"
        "mbarrier.try_wait.parity.acquire.cta.shared::cta.b64 P, [%0], %1;\n\t"
        "@!P bra W%=;\n\t}"
        :: "r"(a), "r"(parity) : "memory");
}
__device__ __forceinline__ void tma2d(unsigned dst, const CUtensorMap* m,
                                      int x, int y, unsigned bar) {
    asm volatile(
        "cp.async.bulk.tensor.2d.shared::cta.global.tile.mbarrier::complete_tx::bytes "
        "[%0], [%1, {%2, %3}], [%4];"
        :: "r"(dst), "l"(m), "r"(x), "r"(y), "r"(bar) : "memory");
}

// ---------------- timelike_mask decode (dtype-robust: f32 / i32 / bool8) ----------------
__global__ void decode_mask_kernel(const void* __restrict__ raw) {
    __shared__ int cls;
    if (threadIdx.x == 0) {
        const unsigned* w = (const unsigned*)raw;
        int isFloat = 0, isByte = 0;
        for (int i = 0; i < 192; i++) {
            unsigned v = w[i];
            if (v == 0x3F800000u) isFloat = 1;
            if (v != 0u) {
                bool bytes01 = true, hi = false;
                for (int b = 0; b < 4; b++) {
                    unsigned by = (v >> (8*b)) & 0xffu;
                    if (by > 1u) bytes01 = false;
                    if (b > 0 && by) hi = true;
                }
                if (bytes01 && hi) isByte = 1;
            }
        }
        cls = isFloat ? 0 : (isByte ? 2 : 1);
    }
    __syncthreads();
    int c = cls;
    for (int i = threadIdx.x; i < DIM; i += blockDim.x) {
        float mv;
        if (c == 0)      mv = ((const float*)raw)[i];
        else if (c == 1) mv = (float)(((const int*)raw)[i] != 0);
        else             mv = (float)(((const unsigned char*)raw)[i] != 0);
        g_mask[i] = mv;
    }
}

// ---------------- fused weight prep: concat + bf16 + mask/scale folding ----------------
#define PR_S0 (QKVLD*DIM)
#define PR_S1 (PR_S0 + (size_t)KCAT*DIM)
#define PR_S2 (PR_S1 + (size_t)DIM*KCAT)
#define PR_S3 (PR_S2 + (size_t)DIM*DIM)
#define PREP_QUADS (PR_S3/4)

__global__ __launch_bounds__(256) void prep_all(
    const float* __restrict__ Wq, const float* __restrict__ Wk,
    const float* __restrict__ Wv, const float* __restrict__ Wo,
    const float* __restrict__ w1, const float* __restrict__ w1t,
    const float* __restrict__ w1s, const float* __restrict__ w2,
    const float* __restrict__ w2t, const float* __restrict__ w2s)
{
    size_t i = (size_t)(blockIdx.x * 256 + threadIdx.x) * 4;
    const float* src;
    bf16* dst;
    float m0 = 1.f, m1 = 1.f, m2 = 1.f, m3 = 1.f;
    if (i < PR_S0) {
        int r = (int)(i / DIM), c = (int)(i % DIM);
        src = (r < DIM) ? (Wq + (size_t)r*DIM + c)
            : (r < 2*DIM) ? (Wk + (size_t)(r-DIM)*DIM + c)
            : (Wv + (size_t)(r-2*DIM)*DIM + c);
        dst = g_wqkv + i;
    } else if (i < PR_S1) {
        size_t j = i - PR_S0;
        int r = (int)(j / DIM), c = (int)(j % DIM);
        if (r < DFF) {
            src = w1 + (size_t)r*DIM + c;
        } else if (r < DFF + DFFH) {
            src = w1t + (size_t)(r-DFF)*DIM + c;
            m0 = g_mask[c]; m1 = g_mask[c+1]; m2 = g_mask[c+2]; m3 = g_mask[c+3];
        } else {
            src = w1s + (size_t)(r-DFF-DFFH)*DIM + c;
            m0 = 1.f-g_mask[c]; m1 = 1.f-g_mask[c+1];
            m2 = 1.f-g_mask[c+2]; m3 = 1.f-g_mask[c+3];
        }
        dst = g_w1cat + j;
    } else if (i < PR_S2) {
        size_t j = i - PR_S1;
        int r = (int)(j / KCAT), c = (int)(j % KCAT);
        src = (c < DFF) ? (w2 + (size_t)r*DFF + c)
            : (c < DFF+DFFH) ? (w2t + (size_t)r*DFFH + c - DFF)
            : (w2s + (size_t)r*DFFH + c - DFF - DFFH);
        dst = g_w2cat + j;
        m0 = m1 = m2 = m3 = 0.5f;                 // fold FFN blend scale
    } else {
        size_t j = i - PR_S2;
        src = Wo + j;
        dst = g_woc + j;
    }
    float4 v = *(const float4*)src;
    *(__nv_bfloat162*)dst       = pack_bf2(v.x * m0, v.y * m1);
    *(__nv_bfloat162*)(dst + 2) = pack_bf2(v.z * m2, v.w * m3);
}

// ---------------- Minkowski LayerNorm (bf16 output) ----------------
__global__ __launch_bounds__(256) void mink_norm_kernel(
    const float* __restrict__ x, const float* __restrict__ w,
    const float* __restrict__ bb, bf16* __restrict__ out)
{
    __shared__ float sA[8], sB[8];
    int row = blockIdx.x, t = threadIdx.x;
    const float* xr = x + (size_t)row * DIM;
    float v0 = xr[t], v1 = xr[t+256], v2 = xr[t+512];
    int lane = t & 31, wp = t >> 5;

    float s = v0 + v1 + v2;
    #pragma unroll
    for (int o = 16; o; o >>= 1) s += __shfl_xor_sync(0xffffffffu, s, o);
    if (!lane) sA[wp] = s;
    __syncthreads();
    float tot = 0.f;
    #pragma unroll
    for (int i = 0; i < 8; i++) tot += sA[i];
    float mean = tot * (1.f / DIM);

    float c0 = v0 - mean, c1 = v1 - mean, c2 = v2 - mean;
    float m0 = g_mask[t], m1 = g_mask[t+256], m2 = g_mask[t+512];
    float s2  = c0*c0 + c1*c1 + c2*c2;
    float s2m = c0*c0*m0 + c1*c1*m1 + c2*c2*m2;
    #pragma unroll
    for (int o = 16; o; o >>= 1) {
        s2  += __shfl_xor_sync(0xffffffffu, s2,  o);
        s2m += __shfl_xor_sync(0xffffffffu, s2m, o);
    }
    __syncthreads();
    if (!lane) { sA[wp] = s2; sB[wp] = s2m; }
    __syncthreads();
    float S2 = 0.f, S2m = 0.f;
    #pragma unroll
    for (int i = 0; i < 8; i++) { S2 += sA[i]; S2m += sB[i]; }

    float var = S2 * (1.f / DIM);
    float eta = S2 - 2.f * S2m;
    float kk  = 0.5f * (rsqrtf(var + 1e-5f) + rsqrtf(fabsf(eta) + 1e-5f));

    size_t o0 = (size_t)row * DIM + t;
    out[o0]     = __float2bfloat16_rn(w[t]     * (c0 * kk) + bb[t]);
    out[o0+256] = __float2bfloat16_rn(w[t+256] * (c1 * kk) + bb[t+256]);
    out[o0+512] = __float2bfloat16_rn(w[t+512] * (c2 * kk) + bb[t+512]);
}

// ---------------- TMA-fed bf16 tensor-core NT GEMM ----------------
// 3-stage ring; per-stage full (TMA tx) + empty (8 warp arrivals) mbarriers.
#define TSTG 3
#define TSTB 32768
#define TC_SMEM (TSTG*TSTB + 1024)

__device__ __forceinline__ void gemm_tma_core(
    const CUtensorMap& mapA, const CUtensorMap& mapB,
    int k0, int nk, int bm, int bn, float (&acc)[4][4][4])
{
    extern __shared__ char tsm[];
    uintptr_t gp = (uintptr_t)tsm;
    unsigned base = (unsigned)__cvta_generic_to_shared(
        (void*)((gp + 1023) & ~(uintptr_t)1023));
    __shared__ __align__(8) unsigned long long mbar_s[2*TSTG];
    unsigned mbF = (unsigned)__cvta_generic_to_shared(mbar_s);
    unsigned mbE = mbF + 8*TSTG;

    int tid = threadIdx.x, lane = tid & 31, wid = tid >> 5;
    int wm = wid & 1, wn = wid >> 1;
    int lrow = lane & 15, lu = lane >> 4;

    if (tid == 0) {
        #pragma unroll
        for (int s = 0; s < TSTG; s++) {
            mbar_init(mbF + 8*s, 1);
            mbar_init(mbE + 8*s, 8);     // one arrival per warp
        }
    }
    __syncthreads();
    if (tid == 0) {
        for (int s = 0; s < TSTG && s < nk; s++) {
            mbar_expect(mbF + 8*s, TSTB);
            tma2d(base + s*TSTB,         &mapA, k0 + s*64, bm, mbF + 8*s);
            tma2d(base + s*TSTB + 16384, &mapB, k0 + s*64, bn, mbF + 8*s);
        }
    }

    for (int kt = 0; kt < nk; kt++) {
        int b = kt % TSTG;
        unsigned par = (unsigned)((kt / TSTG) & 1);
        mbar_wait(mbF + 8*b, par);
        unsigned stA = base + b*TSTB, stB = stA + 16384;
        #pragma unroll
        for (int ks = 0; ks < 4; ks++) {
            unsigned af[4][4], bq[2][4];
            #pragma unroll
            for (int mt = 0; mt < 4; mt++) {
                int r = wm*64 + mt*16 + lrow;
                ldsm4(af[mt], stA + r*128 + ((((ks<<1)|lu) ^ (r&7)) << 4));
            }
            #pragma unroll
            for (int p = 0; p < 2; p++) {
                int r = wn*32 + p*16 + lrow;
                ldsm4(bq[p], stB + r*128 + ((((ks<<1)|lu) ^ (r&7)) << 4));
            }
            #pragma unroll
            for (int mt = 0; mt < 4; mt++)
                #pragma unroll
                for (int nt = 0; nt < 4; nt++)
                    mma16(acc[mt][nt], af[mt],
                          bq[nt>>1][nt&1], bq[nt>>1][(nt&1)+2]);
        }
        if (lane == 0) mbar_arrive(mbE + 8*b);   // this warp done reading stage
        if (tid == 0 && kt + TSTG < nk) {
            mbar_wait(mbE + 8*b, par);           // all 8 warps done with buffer b
            asm volatile("fence.proxy.async.shared::cta;" ::: "memory");
            mbar_expect(mbF + 8*b, TSTB);
            tma2d(stA, &mapA, k0 + (kt + TSTG)*64, bm, mbF + 8*b);
            tma2d(stB, &mapB, k0 + (kt + TSTG)*64, bn, mbF + 8*b);
        }
    }
}

// epilogue: OT 0 fp32(+resid, alpha), 1 bf16 (act), 2 raw fp32 partial
template<int OT>
__device__ __forceinline__ void store_epi4(
    float (&acc)[4][4][4], void* Cv, const float* __restrict__ resid,
    int ldc, float alpha, int bm, int bn, int act)
{
    int tid = threadIdx.x, lane = tid & 31, wid = tid >> 5;
    int wm = wid & 1, wn = wid >> 1;
    int g = lane >> 2, t = lane & 3;
    #pragma unroll
    for (int mt = 0; mt < 4; mt++) {
        int r0 = bm + wm*64 + mt*16 + g;
        #pragma unroll
        for (int nt = 0; nt < 4; nt++) {
            int c = bn + wn*32 + nt*8 + t*2;
            #pragma unroll
            for (int hh = 0; hh < 2; hh++) {
                float v0 = acc[mt][nt][2*hh];
                float v1 = acc[mt][nt][2*hh + 1];
                size_t idx = (size_t)(r0 + 8*hh) * ldc + c;
                if (OT == 1) {
                    if (act == 1) { v0 = gelu_f(v0); v1 = gelu_f(v1); }
                    else if (act == 2) { v0 = silu_f(v0); v1 = silu_f(v1); }
                    *(__nv_bfloat162*)((bf16*)Cv + idx) = pack_bf2(v0, v1);
                } else if (OT == 0) {
                    v0 *= alpha; v1 *= alpha;
                    if (resid) {
                        float2 rv = *(const float2*)(resid + idx);
                        v0 += rv.x; v1 += rv.y;
                    }
                    *(float2*)((float*)Cv + idx) = make_float2(v0, v1);
                } else {
                    *(float2*)((float*)Cv + idx) = make_float2(v0, v1);
                }
            }
        }
    }
}

// fused Lorentz-qeff epilogue for Q tiles (bn < DIM)
__device__ void store_epi_qeff(
    float (&acc)[4][4][4], bf16* __restrict__ C, int ldc, int bm, int bn)
{
    extern __shared__ char tsm[];
    float* sred = (float*)tsm;                 // [8 warps][64 rows][2]
    int tid = threadIdx.x, lane = tid & 31, wid = tid >> 5;
    int wm = wid & 1, wn = wid >> 1;
    int g = lane >> 2, t = lane & 3;
    int pw = wid ^ 2;                          // partner warp: same wm, wn^1

    float mcol[4][2];
    #pragma unroll
    for (int nt = 0; nt < 4; nt++) {
        int c = bn + wn*32 + nt*8 + t*2;
        mcol[nt][0] = g_mask[c];
        mcol[nt][1] = g_mask[c + 1];
    }

    float qn[8], qt[8];
    #pragma unroll
    for (int mt = 0; mt < 4; mt++)
        #pragma unroll
        for (int hh = 0; hh < 2; hh++) {
            float a = 0.f, b = 0.f;
            #pragma unroll
            for (int nt = 0; nt < 4; nt++) {
                float v0 = acc[mt][nt][2*hh], v1 = acc[mt][nt][2*hh + 1];
                a += v0*v0 + v1*v1;
                b += v0*v0*mcol[nt][0] + v1*v1*mcol[nt][1];
            }
            a += __shfl_xor_sync(0xffffffffu, a, 1);
            b += __shfl_xor_sync(0xffffffffu, b, 1);
            a += __shfl_xor_sync(0xffffffffu, a, 2);
            b += __shfl_xor_sync(0xffffffffu, b, 2);
            qn[mt*2 + hh] = a; qt[mt*2 + hh] = b;
        }

    __syncthreads();       // all warps past mainloop; smem ring reusable
    if (t == 0) {
        #pragma unroll
        for (int i = 0; i < 8; i++) {
            int row = (i >> 1) * 16 + g + 8 * (i & 1);
            sred[(wid*64 + row)*2 + 0] = qn[i];
            sred[(wid*64 + row)*2 + 1] = qt[i];
        }
    }
    __syncthreads();

    #pragma unroll
    for (int mt = 0; mt < 4; mt++)
        #pragma unroll
        for (int hh = 0; hh < 2; hh++) {
            int row = mt*16 + g + 8*hh;
            float a = qn[mt*2 + hh] + sred[(pw*64 + row)*2 + 0];
            float b = qt[mt*2 + hh] + sred[(pw*64 + row)*2 + 1];
            float qtn = sqrtf(b);
            float sf = (qtn > 1e-6f) ? sqrtf(a) / fmaxf(qtn, 1e-8f) : 0.f;
            int r0 = bm + wm*64 + row;
            #pragma unroll
            for (int nt = 0; nt < 4; nt++) {
                int c = bn + wn*32 + nt*8 + t*2;
                float v0 = acc[mt][nt][2*hh]   * (1.f - 0.5f*sf*mcol[nt][0]) * 0.125f;
                float v1 = acc[mt][nt][2*hh+1] * (1.f - 0.5f*sf*mcol[nt][1]) * 0.125f;
                *(__nv_bfloat162*)(C + (size_t)r0*ldc + c) = pack_bf2(v0, v1);
            }
        }
}

template<int OT, int ACTSEL, int QEFF>
__global__ __launch_bounds__(256, 2) void tgemm_tma(
    const __grid_constant__ CUtensorMap mapA,
    const __grid_constant__ CUtensorMap mapB,
    void* __restrict__ C, const float* __restrict__ resid,
    int K, int ldc, float alpha)
{
    int bm = blockIdx.y * 128, bn = blockIdx.x * 128;
    float acc[4][4][4] = {};
    gemm_tma_core(mapA, mapB, 0, K >> 6, bm, bn, acc);
    if (QEFF && bn < DIM) {
        store_epi_qeff(acc, (bf16*)C, ldc, bm, bn);
    } else {
        int act = ACTSEL ? ((bn >= DFF && bn < DFF + DFFH) ? 2 : 1) : 0;
        store_epi4<OT>(acc, C, resid, ldc, alpha, bm, bn, act);
    }
}

// split-K down-projection (0.5 pre-folded into w2cat):
// z=0 -> out = x1 + chunk0 ; z>=1 -> pb[z-1] = chunk_z (raw fp32)
__global__ __launch_bounds__(256, 2) void tgemm_down(
    const __grid_constant__ CUtensorMap mapA,
    const __grid_constant__ CUtensorMap mapB,
    float* __restrict__ out, float* __restrict__ pb0,
    const float* __restrict__ resid)
{
    int bm = blockIdx.y * 128, bn = blockIdx.x * 128;
    int z = blockIdx.z;
    float acc[4][4][4] = {};
    gemm_tma_core(mapA, mapB, z * KCHUNK, KCHUNK >> 6, bm, bn, acc);
    if (z == 0) store_epi4<0>(acc, out, resid, DIM, 1.f, bm, bn, 0);
    else        store_epi4<2>(acc, pb0 + (size_t)(z-1)*NROWS*DIM, nullptr,
                              DIM, 0.f, bm, bn, 0);
}

// final: out += pb0 + pb1 + pb2  (scales pre-folded)
__global__ __launch_bounds__(256) void addk4(
    float* __restrict__ out, const float* __restrict__ pb)
{
    int i = blockIdx.x * 256 + threadIdx.x;
    float4 o  = ((const float4*)out)[i];
    float4 p0 = ((const float4*)(pb))[i];
    float4 p1 = ((const float4*)(pb + (size_t)NROWS*DIM))[i];
    float4 p2 = ((const float4*)(pb + (size_t)2*NROWS*DIM))[i];
    ((float4*)out)[i] = make_float4(o.x + p0.x + p1.x + p2.x,
                                    o.y + p0.y + p1.y + p2.y,
                                    o.z + p0.z + p1.z + p2.z,
                                    o.w + p0.w + p1.w + p2.w);
}

// ---------------- bf16 tensor-core causal flash attention ----------------
// V kept ROW-major in smem; P@V uses ldmatrix.trans. K/V tiles filled by cp.async.
#define FSH 72
#define FA_SMEM ((128 + 64 + 64 + 128) * FSH * 2)   // 55296 bytes

__global__ __launch_bounds__(256) void flash_tc(
    const bf16* __restrict__ QKV, bf16* __restrict__ O)
{
    extern __shared__ char smc[];
    bf16* Qs = (bf16*)smc;
    bf16* Ps = Qs + 256 * FSH;
    unsigned smQ = (unsigned)__cvta_generic_to_shared(Qs);
    unsigned smK = smQ + 128 * FSH * 2;
    unsigned smV = smQ + 192 * FSH * 2;
    unsigned smP = smQ + 256 * FSH * 2;

    int tid = threadIdx.x, lane = tid & 31, wid = tid >> 5;
    int g = lane >> 2, t = lane & 3;
    int lrow = lane & 15, lk8 = (lane >> 4) << 3;
    int bid = blockIdx.x;
    int qb = 15 - bid / 24;
    int bh = bid % 24;
    int b = bh / NHEAD, h = bh % NHEAD;

    const bf16* Qp = QKV + (size_t)(b * SEQL + qb * 128) * QKVLD + h * DHEAD;
    const bf16* Kp = QKV + (size_t)(b * SEQL) * QKVLD + DIM + h * DHEAD;
    const bf16* Vp = Kp + DIM;

    #pragma unroll
    for (int it = 0; it < 4; it++) {
        int idx = tid + it * 256;
        int r = idx >> 3, c8 = (idx & 7) * 8;
        *(uint4*)&Qs[r * FSH + c8] = *(const uint4*)(Qp + (size_t)r * QKVLD + c8);
    }

    float oacc[8][4] = {};
    float mrun[2] = {-1e30f, -1e30f}, lrun[2] = {0.f, 0.f};
    int rbase = qb * 128 + wid * 16;
    int kmax = 2 * qb + 2;

    for (int kt = 0; kt < kmax; kt++) {
        __syncthreads();   // previous K/V reads done
        // K and V tiles (both row-major 64 x 64) via cp.async
        #pragma unroll
        for (int it = 0; it < 2; it++) {
            int idx = tid + it * 256;
            int r = idx >> 3, c8 = (idx & 7) * 8;
            size_t go = (size_t)(kt * 64 + r) * QKVLD + c8;
            cp16(smK + (r * FSH + c8) * 2, Kp + go);
            cp16(smV + (r * FSH + c8) * 2, Vp + go);
        }
        cp_commit();
        cp_wait<0>();
        __syncthreads();

        float s[8][4] = {};
        #pragma unroll
        for (int ks = 0; ks < 4; ks++) {
            unsigned aq[4], bk[4][4];
            ldsm4(aq, smQ + ((wid*16 + lrow)*FSH + ks*16 + lk8)*2);
            #pragma unroll
            for (int p = 0; p < 4; p++)
                ldsm4(bk[p], smK + ((p*16 + lrow)*FSH + ks*16 + lk8)*2);
            #pragma unroll
            for (int nt = 0; nt < 8; nt++)
                mma16(s[nt], aq, bk[nt>>1][nt&1], bk[nt>>1][(nt&1)+2]);
        }

        if (kt * 64 + 63 > rbase) {
            int r0 = rbase + g, r1 = r0 + 8;
            #pragma unroll
            for (int nt = 0; nt < 8; nt++) {
                int c0 = kt * 64 + nt * 8 + t * 2;
                if (c0     > r0) s[nt][0] = -1e30f;
                if (c0 + 1 > r0) s[nt][1] = -1e30f;
                if (c0     > r1) s[nt][2] = -1e30f;
                if (c0 + 1 > r1) s[nt][3] = -1e30f;
            }
        }

        #pragma unroll
        for (int r = 0; r < 2; r++) {
            float rm = -1e30f;
            #pragma unroll
            for (int nt = 0; nt < 8; nt++)
                rm = fmaxf(rm, fmaxf(s[nt][2*r], s[nt][2*r + 1]));
            rm = fmaxf(rm, __shfl_xor_sync(0xffffffffu, rm, 1));
            rm = fmaxf(rm, __shfl_xor_sync(0xffffffffu, rm, 2));
            float mn = fmaxf(mrun[r], rm);
            float sc = __expf(mrun[r] - mn);
            float rs = 0.f;
            #pragma unroll
            for (int nt = 0; nt < 8; nt++) {
                s[nt][2*r]     = __expf(s[nt][2*r]     - mn);
                s[nt][2*r + 1] = __expf(s[nt][2*r + 1] - mn);
                rs += s[nt][2*r] + s[nt][2*r + 1];
            }
            rs += __shfl_xor_sync(0xffffffffu, rs, 1);
            rs += __shfl_xor_sync(0xffffffffu, rs, 2);
            lrun[r] = lrun[r] * sc + rs;
            mrun[r] = mn;
            #pragma unroll
            for (int nt = 0; nt < 8; nt++) {
                oacc[nt][2*r]     *= sc;
                oacc[nt][2*r + 1] *= sc;
            }
        }

        #pragma unroll
        for (int nt = 0; nt < 8; nt++) {
            int c = nt * 8 + t * 2;
            *(__nv_bfloat162*)&Ps[(wid*16 + g    ) * FSH + c] = pack_bf2(s[nt][0], s[nt][1]);
            *(__nv_bfloat162*)&Ps[(wid*16 + g + 8) * FSH + c] = pack_bf2(s[nt][2], s[nt][3]);
        }
        __syncwarp();

        // O += P @ V  (V row-major; B fragments via ldmatrix.trans)
        #pragma unroll
        for (int ks = 0; ks < 4; ks++) {
            unsigned ap[4], bv[4][4];
            ldsm4(ap, smP + ((wid*16 + lrow)*FSH + ks*16 + lk8)*2);
            #pragma unroll
            for (int p = 0; p < 4; p++)
                ldsm4t(bv[p], smV + ((ks*16 + lrow)*FSH + p*16 + lk8)*2);
            #pragma unroll
            for (int nt = 0; nt < 8; nt++)
                mma16(oacc[nt], ap, bv[nt>>1][(nt&1)*2], bv[nt>>1][(nt&1)*2+1]);
        }
    }

    float i0 = 1.f / lrun[0], i1 = 1.f / lrun[1];
    size_t grow0 = (size_t)b * SEQL + qb * 128 + wid * 16 + g;
    #pragma unroll
    for (int nt = 0; nt < 8; nt++) {
        int c = h * DHEAD + nt * 8 + t * 2;
        *(__nv_bfloat162*)&O[grow0 * DIM + c] =
            pack_bf2(oacc[nt][0] * i0, oacc[nt][1] * i0);
        *(__nv_bfloat162*)&O[(grow0 + 8) * DIM + c] =
            pack_bf2(oacc[nt][2] * i1, oacc[nt][3] * i1);
    }
}

// ---------------- host launcher ----------------
typedef CUresult (*tmap_fn_t)(
    CUtensorMap*, CUtensorMapDataType, cuuint32_t, void*,
    const cuuint64_t*, const cuuint64_t*, const cuuint32_t*, const cuuint32_t*,
    CUtensorMapInterleave, CUtensorMapSwizzle, CUtensorMapL2promotion,
    CUtensorMapFloatOOBfill);

static void encode_map(tmap_fn_t fn, CUtensorMap* m, void* p,
                       unsigned long long Kd, unsigned long long Md) {
    cuuint64_t dims[2]    = {Kd, Md};
    cuuint64_t strides[1] = {Kd * 2};
    cuuint32_t box[2]     = {64, 128};
    cuuint32_t es[2]      = {1, 1};
    fn(m, CU_TENSOR_MAP_DATA_TYPE_BFLOAT16, 2, p, dims, strides, box, es,
       CU_TENSOR_MAP_INTERLEAVE_NONE, CU_TENSOR_MAP_SWIZZLE_128B,
       CU_TENSOR_MAP_L2_PROMOTION_L2_128B, CU_TENSOR_MAP_FLOAT_OOB_FILL_NONE);
}

extern "C" void kernel_launch(void* const* d_in, const int* in_sizes, int n_in,
                              void* d_out, int out_size)
{
    const float* x    = (const float*)d_in[0];
    const void*  tmsk = d_in[2];
    const float* Wq   = (const float*)d_in[3];
    const float* Wk   = (const float*)d_in[4];
    const float* Wv   = (const float*)d_in[5];
    const float* Wo   = (const float*)d_in[6];
    const float* w1   = (const float*)d_in[7];
    const float* w2   = (const float*)d_in[8];
    const float* w1t  = (const float*)d_in[9];
    const float* w2t  = (const float*)d_in[10];
    const float* w1s  = (const float*)d_in[11];
    const float* w2s  = (const float*)d_in[12];
    const float* n1w  = (const float*)d_in[13];
    const float* n1b  = (const float*)d_in[14];
    const float* n2w  = (const float*)d_in[15];
    const float* n2b  = (const float*)d_in[16];
    float* out = (float*)d_out;

    bf16 *p_xn, *p_qkv, *p_attn, *p_hcat;
    bf16 *p_wqkv, *p_w1cat, *p_w2cat, *p_woc;
    float *p_x1, *p_pb;
    cudaGetSymbolAddress((void**)&p_xn,    g_xn);
    cudaGetSymbolAddress((void**)&p_qkv,   g_qkv);
    cudaGetSymbolAddress((void**)&p_attn,  g_attn);
    cudaGetSymbolAddress((void**)&p_x1,    g_x1);
    cudaGetSymbolAddress((void**)&p_pb,    g_pb);
    cudaGetSymbolAddress((void**)&p_hcat,  g_hcat);
    cudaGetSymbolAddress((void**)&p_wqkv,  g_wqkv);
    cudaGetSymbolAddress((void**)&p_w1cat, g_w1cat);
    cudaGetSymbolAddress((void**)&p_w2cat, g_w2cat);
    cudaGetSymbolAddress((void**)&p_woc,   g_woc);

    static tmap_fn_t tmap_fn = nullptr;
    static int attr_done = 0;
    if (!attr_done) {
        cudaFuncSetAttribute((const void*)tgemm_tma<1,0,1>, cudaFuncAttributeMaxDynamicSharedMemorySize, TC_SMEM);
        cudaFuncSetAttribute((const void*)tgemm_tma<0,0,0>, cudaFuncAttributeMaxDynamicSharedMemorySize, TC_SMEM);
        cudaFuncSetAttribute((const void*)tgemm_tma<1,1,0>, cudaFuncAttributeMaxDynamicSharedMemorySize, TC_SMEM);
        cudaFuncSetAttribute((const void*)tgemm_down,       cudaFuncAttributeMaxDynamicSharedMemorySize, TC_SMEM);
        cudaFuncSetAttribute((const void*)flash_tc,         cudaFuncAttributeMaxDynamicSharedMemorySize, FA_SMEM);
        cudaDriverEntryPointQueryResult qr;
        cudaGetDriverEntryPoint("cuTensorMapEncodeTiled", (void**)&tmap_fn,
                                cudaEnableDefault, &qr);
        attr_done = 1;
    }

    // tensormaps (encoded on host; captured as kernel params)
    CUtensorMap mXn, mAttn, mHcat, mWqkv, mWoc, mW1, mW2;
    encode_map(tmap_fn, &mXn,   p_xn,    DIM,  NROWS);
    encode_map(tmap_fn, &mAttn, p_attn,  DIM,  NROWS);
    encode_map(tmap_fn, &mHcat, p_hcat,  KCAT, NROWS);
    encode_map(tmap_fn, &mWqkv, p_wqkv,  DIM,  QKVLD);
    encode_map(tmap_fn, &mWoc,  p_woc,   DIM,  DIM);
    encode_map(tmap_fn, &mW1,   p_w1cat, DIM,  KCAT);
    encode_map(tmap_fn, &mW2,   p_w2cat, KCAT, DIM);

    decode_mask_kernel<<<1, 256>>>(tmsk);
    prep_all<<<PREP_QUADS/256, 256>>>(Wq, Wk, Wv, Wo, w1, w1t, w1s, w2, w2t, w2s);

    // ---- attention path ----
    mink_norm_kernel<<<NROWS, 256>>>(x, n1w, n1b, p_xn);

    // QKV with fused Lorentz-qeff epilogue on Q tiles
    tgemm_tma<1,0,1><<<dim3(QKVLD/128, NROWS/128), 256, TC_SMEM>>>(
        mXn, mWqkv, p_qkv, nullptr, DIM, QKVLD, 1.f);

    flash_tc<<<16 * 24, 256, FA_SMEM>>>(p_qkv, p_attn);

    // x1 = x + attn @ Wo^T
    tgemm_tma<0,0,0><<<dim3(DIM/128, NROWS/128), 256, TC_SMEM>>>(
        mAttn, mWoc, p_x1, x, DIM, DIM, 1.f);

    // ---- FFN path ----
    mink_norm_kernel<<<NROWS, 256>>>(p_x1, n2w, n2b, p_xn);

    tgemm_tma<1,1,0><<<dim3(KCAT/128, NROWS/128), 256, TC_SMEM>>>(
        mXn, mW1, p_hcat, nullptr, DIM, KCAT, 1.f);

    // down-projection, split-K=4 (0.5 pre-folded into w2cat)
    tgemm_down<<<dim3(DIM/128, NROWS/128, KSPLIT), 256, TC_SMEM>>>(
        mHcat, mW2, out, p_pb, p_x1);

    // out += pb0 + pb1 + pb2
    addk4<<<NROWS*DIM/4/256, 256>>>(out, p_pb);
}